// round 1
// baseline (speedup 1.0000x reference)
#include <cuda_runtime.h>

#define NN 4096
#define FF 512
#define DD 64
#define HH 8

// Scratch: Wh[NN*FF] + hcat[NN*FF] + Who[NN*DD] + h2[NN*DD] + main f arrays (6*HH*NN) + out-head f arrays (6*NN)
__device__ float g_scratch[2*NN*FF + 2*NN*DD + 6*HH*NN + 6*NN];
__device__ unsigned g_bits[NN*(NN/32)];

// ---------------- adj -> bitmask ----------------
__global__ void k_bits(const int* __restrict__ adj, unsigned* __restrict__ bits) {
    int gw = (blockIdx.x * blockDim.x + threadIdx.x) >> 5;
    int lane = threadIdx.x & 31;
    if (gw >= NN*(NN/32)) return;
    int v = adj[(size_t)gw*32 + lane];
    unsigned b = __ballot_sync(0xFFFFFFFFu, v > 0);
    if (lane == 0) bits[gw] = b;
}

// ---------------- generic tiled GEMM: C[M,*] = A[M,K] @ B ----------------
// headed=1: B[f,col] = W[(col>>6)*K*64 + f*64 + (col&63)]   (W is [H,F,D])
// headed=0: B[f,col] = B[f*ldb + col]
__global__ __launch_bounds__(256) void k_gemm(
    const float* __restrict__ A, int lda,
    const float* __restrict__ B, int ldb, int headed,
    float* __restrict__ C, int ldc, int K)
{
    __shared__ float As[16][128];
    __shared__ float Bs[16][64];
    int t = threadIdx.x;
    int n0 = blockIdx.x * 128;
    int c0 = blockIdx.y * 64;
    int rg = t >> 4, cg = t & 15;
    float acc[8][4];
    #pragma unroll
    for (int i = 0; i < 8; i++)
        #pragma unroll
        for (int j = 0; j < 4; j++) acc[i][j] = 0.f;

    for (int k0 = 0; k0 < K; k0 += 16) {
        #pragma unroll
        for (int i = 0; i < 2; i++) {
            int lin = t + i*256;       // 0..511
            int r = lin >> 2;          // 128 rows
            int q = lin & 3;           // 4 float4 per row
            float4 v = *(const float4*)(A + (size_t)(n0+r)*lda + k0 + q*4);
            As[q*4+0][r] = v.x; As[q*4+1][r] = v.y;
            As[q*4+2][r] = v.z; As[q*4+3][r] = v.w;
        }
        {
            int kk = t >> 4;
            int c4 = t & 15;
            int col = c0 + c4*4;
            const float* bp = headed
                ? B + (size_t)(col >> 6)*(size_t)(K*64) + (size_t)(k0+kk)*64 + (col & 63)
                : B + (size_t)(k0+kk)*ldb + col;
            float4 v = *(const float4*)bp;
            *(float4*)&Bs[kk][c4*4] = v;
        }
        __syncthreads();
        #pragma unroll
        for (int kk = 0; kk < 16; kk++) {
            float a[8], b[4];
            *(float4*)&a[0] = *(const float4*)&As[kk][rg*8];
            *(float4*)&a[4] = *(const float4*)&As[kk][rg*8 + 4];
            *(float4*)&b[0] = *(const float4*)&Bs[kk][cg*4];
            #pragma unroll
            for (int i = 0; i < 8; i++)
                #pragma unroll
                for (int j = 0; j < 4; j++)
                    acc[i][j] += a[i]*b[j];
        }
        __syncthreads();
    }
    #pragma unroll
    for (int i = 0; i < 8; i++) {
        float4 v; v.x = acc[i][0]; v.y = acc[i][1]; v.z = acc[i][2]; v.w = acc[i][3];
        *(float4*)(C + (size_t)(n0 + rg*8 + i)*ldc + c0 + cg*4) = v;
    }
}

// ------------- per-(head,node) attention scalars + exp factorization -------------
__global__ void k_fexp(const float* __restrict__ Wh, int ld,
    const float* __restrict__ asrc, const float* __restrict__ adst,
    float* __restrict__ fsrc, float* __restrict__ fdst,
    float* __restrict__ Ap, float* __restrict__ An,
    float* __restrict__ Bp, float* __restrict__ Bn, int H)
{
    int gw = (blockIdx.x*blockDim.x + threadIdx.x) >> 5;
    int lane = threadIdx.x & 31;
    if (gw >= H*NN) return;
    int h = gw / NN, n = gw % NN;
    const float* row = Wh + (size_t)n*ld + h*64;
    float v0 = row[lane], v1 = row[lane+32];
    float fs = v0*asrc[h*64+lane] + v1*asrc[h*64+lane+32];
    float fd = v0*adst[h*64+lane] + v1*adst[h*64+lane+32];
    #pragma unroll
    for (int o = 16; o; o >>= 1) {
        fs += __shfl_xor_sync(0xFFFFFFFFu, fs, o);
        fd += __shfl_xor_sync(0xFFFFFFFFu, fd, o);
    }
    if (lane == 0) {
        fsrc[gw] = fs; fdst[gw] = fd;
        Ap[gw] = expf(fs);      An[gw] = expf(0.2f*fs);
        Bp[gw] = expf(fd);      Bn[gw] = expf(0.2f*fd);
    }
}

// ------------- fused masked-softmax attention aggregation -------------
// out[n, head*64+d] = (Sum_m w[n,m] * Wh[m, head*64+d]) / (Sum_m w[n,m]),  optional ELU
// w[n,m] = adj[n,m] ? (s>=0 ? Ap[n]*Bp[m] : An[n]*Bn[m]),  s = fsrc[n]+fdst[m]
__global__ __launch_bounds__(256) void k_attn(
    const float* __restrict__ Wh, int ldwh,
    const float* __restrict__ fsrc, const float* __restrict__ fdst,
    const float* __restrict__ Ap, const float* __restrict__ An,
    const float* __restrict__ Bp, const float* __restrict__ Bn,
    const unsigned* __restrict__ bits,
    float* __restrict__ out, int ldout, int applyElu)
{
    extern __shared__ float smf[];
    float* ws   = smf;                  // [128 m][128 r]
    float* whs  = smf + 128*128;        // [128 m][64 d]
    float* fd_s = whs + 128*64;         // 128
    float* Bp_s = fd_s + 128;           // 128
    float* Bn_s = Bp_s + 128;           // 128
    float* ds   = Bn_s + 128;           // 256 (2 partials per row)

    int t = threadIdx.x;
    int head = blockIdx.y;
    int n0 = blockIdx.x * 128;
    int r_st = t & 127;                 // staging row
    int mh = t >> 7;                    // staging m parity (0/1)
    int fbase = head * NN;
    float fsrc_r = fsrc[fbase + n0 + r_st];
    float Ap_r = Ap[fbase + n0 + r_st];
    float An_r = An[fbase + n0 + r_st];
    const unsigned* bitrow = bits + (size_t)(n0 + r_st)*(NN/32);

    int rg = t >> 4, cg = t & 15;
    float acc[8][4];
    #pragma unroll
    for (int i = 0; i < 8; i++)
        #pragma unroll
        for (int j = 0; j < 4; j++) acc[i][j] = 0.f;
    float dsum = 0.f;
    int coloff = head * 64;

    for (int m0 = 0; m0 < NN; m0 += 128) {
        __syncthreads();   // previous GEMM done before overwriting smem
        // stage Wh tile [128 x 64]
        #pragma unroll
        for (int i = 0; i < 8; i++) {
            int lin = t + i*256;          // 0..2047 float4s
            int mm = lin >> 4;
            int q = lin & 15;
            float4 v = *(const float4*)(Wh + (size_t)(m0+mm)*ldwh + coloff + q*4);
            *(float4*)&whs[mm*64 + q*4] = v;
        }
        if (t < 128) {
            fd_s[t] = fdst[fbase + m0 + t];
            Bp_s[t] = Bp[fbase + m0 + t];
            Bn_s[t] = Bn[fbase + m0 + t];
        }
        __syncthreads();
        // compute w tile (each thread: fixed row r_st, m = mh + 2j)
        unsigned wb0 = bitrow[(m0 >> 5) + 0];
        unsigned wb1 = bitrow[(m0 >> 5) + 1];
        unsigned wb2 = bitrow[(m0 >> 5) + 2];
        unsigned wb3 = bitrow[(m0 >> 5) + 3];
        #pragma unroll
        for (int j = 0; j < 64; j++) {
            int m = mh + 2*j;
            float s = fsrc_r + fd_s[m];
            float w = (s >= 0.f) ? (Ap_r * Bp_s[m]) : (An_r * Bn_s[m]);
            unsigned word = (j < 16) ? wb0 : (j < 32) ? wb1 : (j < 48) ? wb2 : wb3;
            unsigned bit = (word >> (((2*j) & 31) + mh)) & 1u;
            w = bit ? w : 0.f;
            ws[m*128 + r_st] = w;
            dsum += w;
        }
        __syncthreads();
        // register-tiled GEMM: acc += ws^T @ whs
        #pragma unroll 8
        for (int k = 0; k < 128; k++) {
            float a[8], b[4];
            *(float4*)&a[0] = *(const float4*)&ws[k*128 + rg*8];
            *(float4*)&a[4] = *(const float4*)&ws[k*128 + rg*8 + 4];
            *(float4*)&b[0] = *(const float4*)&whs[k*64 + cg*4];
            #pragma unroll
            for (int i = 0; i < 8; i++)
                #pragma unroll
                for (int j = 0; j < 4; j++)
                    acc[i][j] += a[i]*b[j];
        }
    }
    ds[mh*128 + r_st] = dsum;
    __syncthreads();
    #pragma unroll
    for (int i = 0; i < 8; i++) {
        int r = rg*8 + i;
        float inv = 1.0f / (ds[r] + ds[128 + r]);
        float vv[4];
        #pragma unroll
        for (int j = 0; j < 4; j++) {
            float z = acc[i][j] * inv;
            if (applyElu) z = (z > 0.f) ? z : expm1f(z);
            vv[j] = z;
        }
        float4 v; v.x = vv[0]; v.y = vv[1]; v.z = vv[2]; v.w = vv[3];
        *(float4*)(out + (size_t)(n0 + r)*ldout + coloff + cg*4) = v;
    }
}

// ------------- ELU + row log_softmax over 64 features -------------
__global__ void k_final(const float* __restrict__ h2, float* __restrict__ out) {
    int gw = (blockIdx.x*blockDim.x + threadIdx.x) >> 5;
    int lane = threadIdx.x & 31;
    if (gw >= NN) return;
    const float* row = h2 + (size_t)gw*64;
    float z0 = row[lane], z1 = row[lane+32];
    z0 = (z0 > 0.f) ? z0 : expm1f(z0);
    z1 = (z1 > 0.f) ? z1 : expm1f(z1);
    float mx = fmaxf(z0, z1);
    #pragma unroll
    for (int o = 16; o; o >>= 1) mx = fmaxf(mx, __shfl_xor_sync(0xFFFFFFFFu, mx, o));
    float se = expf(z0 - mx) + expf(z1 - mx);
    #pragma unroll
    for (int o = 16; o; o >>= 1) se += __shfl_xor_sync(0xFFFFFFFFu, se, o);
    float lse = mx + logf(se);
    out[(size_t)gw*64 + lane]      = z0 - lse;
    out[(size_t)gw*64 + lane + 32] = z1 - lse;
}

extern "C" void kernel_launch(void* const* d_in, const int* in_sizes, int n_in,
                              void* d_out, int out_size)
{
    const float* x     = (const float*)d_in[0];
    const int*   adj   = (const int*)  d_in[1];
    const float* W     = (const float*)d_in[2];
    const float* asrc  = (const float*)d_in[3];
    const float* adst  = (const float*)d_in[4];
    const float* Wo    = (const float*)d_in[5];
    const float* aosrc = (const float*)d_in[6];
    const float* aodst = (const float*)d_in[7];
    float* out = (float*)d_out;

    void* sp = nullptr;  cudaGetSymbolAddress(&sp, g_scratch);
    void* bpv = nullptr; cudaGetSymbolAddress(&bpv, g_bits);
    float* S = (float*)sp;
    unsigned* bits = (unsigned*)bpv;

    float* Wh   = S;
    float* hcat = Wh   + (size_t)NN*FF;
    float* Who  = hcat + (size_t)NN*FF;
    float* h2   = Who  + (size_t)NN*DD;
    float* fm   = h2   + (size_t)NN*DD;
    float* fsrc = fm;
    float* fdst = fm + 1*HH*NN;
    float* Ap   = fm + 2*HH*NN;
    float* An   = fm + 3*HH*NN;
    float* Bp   = fm + 4*HH*NN;
    float* Bn   = fm + 5*HH*NN;
    float* fo   = fm + 6*HH*NN;
    float* ofsrc = fo;        float* ofdst = fo + NN;
    float* oAp = fo + 2*NN;   float* oAn = fo + 3*NN;
    float* oBp = fo + 4*NN;   float* oBn = fo + 5*NN;

    // 1) adj -> bitmask
    {
        long long threads = (long long)NN*(NN/32)*32;
        k_bits<<<(unsigned)((threads + 255)/256), 256>>>(adj, bits);
    }
    // 2) Wh = x @ W (all 8 heads, stored [n, h*64+d])
    k_gemm<<<dim3(NN/128, FF/64), 256>>>(x, FF, W, 0, 1, Wh, FF, FF);
    // 3) attention scalars + exp factorization (main heads)
    k_fexp<<<(HH*NN*32 + 255)/256, 256>>>(Wh, FF, asrc, adst,
                                          fsrc, fdst, Ap, An, Bp, Bn, HH);
    // 4) fused masked softmax-aggregation per head, ELU, write h_cat
    int smemB = (128*128 + 128*64 + 3*128 + 256) * 4;
    cudaFuncSetAttribute(k_attn, cudaFuncAttributeMaxDynamicSharedMemorySize, smemB);
    k_attn<<<dim3(NN/128, HH), 256, smemB>>>(Wh, FF, fsrc, fdst, Ap, An, Bp, Bn,
                                             bits, hcat, FF, 1);
    // 5) Who = h_cat @ W_o
    k_gemm<<<dim3(NN/128, DD/64), 256>>>(hcat, FF, Wo, DD, 0, Who, DD, FF);
    // 6) output-head attention scalars
    k_fexp<<<(NN*32 + 255)/256, 256>>>(Who, DD, aosrc, aodst,
                                       ofsrc, ofdst, oAp, oAn, oBp, oBn, 1);
    // 7) output-head attention (no ELU)
    k_attn<<<dim3(NN/128, 1), 256, smemB>>>(Who, DD, ofsrc, ofdst, oAp, oAn, oBp, oBn,
                                            bits, h2, DD, 0);
    // 8) ELU + log_softmax -> d_out
    k_final<<<(NN*32 + 255)/256, 256>>>(h2, out);
}

// round 3
// speedup vs baseline: 2.2950x; 2.2950x over previous
#include <cuda_runtime.h>
#include <cuda_bf16.h>
#include <cstdint>

#define NN 4096
#define FF 512
#define DD 64
#define HH 8
#define SPLIT 8

// ---------------------------------------------------------------- mma helpers
__device__ __forceinline__ void mma_bf16(float* d, const uint32_t* a, const uint32_t* b) {
    asm volatile("mma.sync.aligned.m16n8k16.row.col.f32.bf16.bf16.f32 "
        "{%0,%1,%2,%3}, {%4,%5,%6,%7}, {%8,%9}, {%0,%1,%2,%3};"
        : "+f"(d[0]), "+f"(d[1]), "+f"(d[2]), "+f"(d[3])
        : "r"(a[0]), "r"(a[1]), "r"(a[2]), "r"(a[3]), "r"(b[0]), "r"(b[1]));
}
__device__ __forceinline__ void ldsm_x4(uint32_t* r, uint32_t addr) {
    asm volatile("ldmatrix.sync.aligned.m8n8.x4.shared.b16 {%0,%1,%2,%3}, [%4];"
        : "=r"(r[0]), "=r"(r[1]), "=r"(r[2]), "=r"(r[3]) : "r"(addr));
}
__device__ __forceinline__ uint32_t smem_to_u32(const void* p) {
    uint32_t a;
    asm("{ .reg .u64 t; cvta.to.shared.u64 t, %1; cvt.u32.u64 %0, t; }" : "=r"(a) : "l"(p));
    return a;
}
__device__ __forceinline__ uint32_t pack_bf2(float a, float b) {
    __nv_bfloat162 p = __floats2bfloat162_rn(a, b);
    return *(uint32_t*)&p;
}

// ---------------------------------------------------------------- scratch
// floats: Wh + hcat (2*NN*FF) + Who + h2 (2*NN*DD) + main f (6*HH*NN) + out f (6*NN)
//         + pnum (SPLIT*NN*DD) + pden (SPLIT*NN)
__device__ float g_scratch[2*NN*FF + 2*NN*DD + 6*HH*NN + 6*NN + SPLIT*NN*DD + SPLIT*NN];
__device__ unsigned g_bits[NN*(NN/32)];
__device__ __nv_bfloat16 g_bf[2*NN*FF + 2*NN*DD];

// ---------------- adj -> bitmask ----------------
__global__ void k_bits(const int* __restrict__ adj, unsigned* __restrict__ bits) {
    int gw = (blockIdx.x * blockDim.x + threadIdx.x) >> 5;
    int lane = threadIdx.x & 31;
    if (gw >= NN*(NN/32)) return;
    int v = adj[(size_t)gw*32 + lane];
    unsigned b = __ballot_sync(0xFFFFFFFFu, v > 0);
    if (lane == 0) bits[gw] = b;
}

// ---------------- generic tiled GEMM (SIMT fp32) ----------------
__global__ __launch_bounds__(256) void k_gemm(
    const float* __restrict__ A, int lda,
    const float* __restrict__ B, int ldb, int headed,
    float* __restrict__ C, int ldc, int K)
{
    __shared__ float As[16][128];
    __shared__ float Bs[16][64];
    int t = threadIdx.x;
    int n0 = blockIdx.x * 128;
    int c0 = blockIdx.y * 64;
    int rg = t >> 4, cg = t & 15;
    float acc[8][4];
    #pragma unroll
    for (int i = 0; i < 8; i++)
        #pragma unroll
        for (int j = 0; j < 4; j++) acc[i][j] = 0.f;

    for (int k0 = 0; k0 < K; k0 += 16) {
        #pragma unroll
        for (int i = 0; i < 2; i++) {
            int lin = t + i*256;
            int r = lin >> 2;
            int q = lin & 3;
            float4 v = *(const float4*)(A + (size_t)(n0+r)*lda + k0 + q*4);
            As[q*4+0][r] = v.x; As[q*4+1][r] = v.y;
            As[q*4+2][r] = v.z; As[q*4+3][r] = v.w;
        }
        {
            int kk = t >> 4;
            int c4 = t & 15;
            int col = c0 + c4*4;
            const float* bp = headed
                ? B + (size_t)(col >> 6)*(size_t)(K*64) + (size_t)(k0+kk)*64 + (col & 63)
                : B + (size_t)(k0+kk)*ldb + col;
            float4 v = *(const float4*)bp;
            *(float4*)&Bs[kk][c4*4] = v;
        }
        __syncthreads();
        #pragma unroll
        for (int kk = 0; kk < 16; kk++) {
            float a[8], b[4];
            *(float4*)&a[0] = *(const float4*)&As[kk][rg*8];
            *(float4*)&a[4] = *(const float4*)&As[kk][rg*8 + 4];
            *(float4*)&b[0] = *(const float4*)&Bs[kk][cg*4];
            #pragma unroll
            for (int i = 0; i < 8; i++)
                #pragma unroll
                for (int j = 0; j < 4; j++)
                    acc[i][j] += a[i]*b[j];
        }
        __syncthreads();
    }
    #pragma unroll
    for (int i = 0; i < 8; i++) {
        float4 v; v.x = acc[i][0]; v.y = acc[i][1]; v.z = acc[i][2]; v.w = acc[i][3];
        *(float4*)(C + (size_t)(n0 + rg*8 + i)*ldc + c0 + cg*4) = v;
    }
}

// ------------- per-(head,node) attention scalars + exp factorization -------------
__global__ void k_fexp(const float* __restrict__ Wh, int ld,
    const float* __restrict__ asrc, const float* __restrict__ adst,
    float* __restrict__ fsrc, float* __restrict__ fdst,
    float* __restrict__ Ap, float* __restrict__ An,
    float* __restrict__ Bp, float* __restrict__ Bn, int H)
{
    int gw = (blockIdx.x*blockDim.x + threadIdx.x) >> 5;
    int lane = threadIdx.x & 31;
    if (gw >= H*NN) return;
    int h = gw / NN, n = gw % NN;
    const float* row = Wh + (size_t)n*ld + h*64;
    float v0 = row[lane], v1 = row[lane+32];
    float fs = v0*asrc[h*64+lane] + v1*asrc[h*64+lane+32];
    float fd = v0*adst[h*64+lane] + v1*adst[h*64+lane+32];
    #pragma unroll
    for (int o = 16; o; o >>= 1) {
        fs += __shfl_xor_sync(0xFFFFFFFFu, fs, o);
        fd += __shfl_xor_sync(0xFFFFFFFFu, fd, o);
    }
    if (lane == 0) {
        fsrc[gw] = fs; fdst[gw] = fd;
        Ap[gw] = expf(fs);      An[gw] = expf(0.2f*fs);
        Bp[gw] = expf(fd);      Bn[gw] = expf(0.2f*fd);
    }
}

// ------------- transpose + bf16 hi/lo split: A[NN][C] -> T_hi/T_lo[C][NN] -------------
__global__ __launch_bounds__(256) void k_tsplit(const float* __restrict__ A, int C,
    __nv_bfloat16* __restrict__ Thi, __nv_bfloat16* __restrict__ Tlo)
{
    __shared__ float tile[32][33];
    int n0 = blockIdx.x*32, c0 = blockIdx.y*32;
    int tx = threadIdx.x & 31, ty = threadIdx.x >> 5;
    #pragma unroll
    for (int i = 0; i < 4; i++) {
        int nr = ty*4 + i;
        tile[nr][tx] = A[(size_t)(n0+nr)*C + c0 + tx];
    }
    __syncthreads();
    #pragma unroll
    for (int i = 0; i < 4; i++) {
        int cr = ty*4 + i;
        float v = tile[tx][cr];
        __nv_bfloat16 h = __float2bfloat16(v);
        Thi[(size_t)(c0+cr)*NN + n0 + tx] = h;
        Tlo[(size_t)(c0+cr)*NN + n0 + tx] = __float2bfloat16(v - __bfloat162float(h));
    }
}

// ------------- mma.sync fused masked-softmax aggregation -------------
// smem byte offsets (w rows padded to 72 bf16 = 144B -> conflict-free ldmatrix)
#define W_HI 0
#define W_LO 18432
#define V_HI 36864
#define V_LO 46080
#define S_FD 55296
#define S_BP 55552
#define S_BN 55808
#define S_DS 56064
#define SMEM_MMA 57088

__global__ __launch_bounds__(256) void k_attn_mma(
    const __nv_bfloat16* __restrict__ WhT_hi,
    const __nv_bfloat16* __restrict__ WhT_lo,
    const float* __restrict__ fsrc, const float* __restrict__ fdst,
    const float* __restrict__ Ap, const float* __restrict__ An,
    const float* __restrict__ Bp, const float* __restrict__ Bn,
    const unsigned* __restrict__ bits,
    float* __restrict__ out, int ldout, int applyElu,
    int mPerCta, float* __restrict__ pnum, float* __restrict__ pden, int partial)
{
    extern __shared__ char smem[];
    uint32_t sb = smem_to_u32(smem);
    float* fd_s = (float*)(smem + S_FD);
    float* Bp_s = (float*)(smem + S_BP);
    float* Bn_s = (float*)(smem + S_BN);
    float* ds   = (float*)(smem + S_DS);

    int t = threadIdx.x;
    int wid = t >> 5, lane = t & 31;
    int head = blockIdx.y;
    int seg = blockIdx.z;
    int n0 = blockIdx.x * 128;
    int r = t & 127, mh = t >> 7;
    int fbase = head * NN;
    int coloff = head * 64;
    int mStart = seg * mPerCta;

    float fsrc_r = fsrc[fbase + n0 + r];
    float Ap_r = Ap[fbase + n0 + r];
    float An_r = An[fbase + n0 + r];
    const unsigned* bitrow = bits + (size_t)(n0 + r) * (NN/32);

    // per-lane ldmatrix byte offsets
    int mrow = wid*16 + (lane & 7) + ((lane >> 3) & 1)*8;
    uint32_t aOff = (uint32_t)(mrow*72 + (lane >> 4)*8) * 2;     // + kbase*2
    uint32_t bOff = (uint32_t)((lane & 7)*72 + (lane >> 3)*8) * 2; // + dt*1152 + ko*64

    float acc[8][4];
    #pragma unroll
    for (int i = 0; i < 8; i++)
        #pragma unroll
        for (int j = 0; j < 4; j++) acc[i][j] = 0.f;
    float dsum = 0.f;

    for (int it = 0; it < mPerCta/64; it++) {
        int m0 = mStart + it*64;
        __syncthreads();
        // stage per-m scalars
        if (t < 64) {
            fd_s[t] = fdst[fbase + m0 + t];
            Bp_s[t] = Bp[fbase + m0 + t];
            Bn_s[t] = Bn[fbase + m0 + t];
        }
        // stage vT tiles: [64 d][64 m] bf16, padded stride 72
        #pragma unroll
        for (int i = 0; i < 2; i++) {
            int idx = t + i*256;
            int d = idx >> 3, k8 = idx & 7;
            uint32_t so = (uint32_t)(d*72 + k8*8)*2;
            *(uint4*)(smem + V_HI + so) = *(const uint4*)(WhT_hi + (size_t)(coloff + d)*NN + m0 + k8*8);
            *(uint4*)(smem + V_LO + so) = *(const uint4*)(WhT_lo + (size_t)(coloff + d)*NN + m0 + k8*8);
        }
        __syncthreads();
        // compute w (row r, local m = mh*32 + j), split hi/lo, STS padded
        unsigned word = bitrow[(m0 >> 5) + mh];
        #pragma unroll
        for (int c = 0; c < 4; c++) {
            uint4 ph, pl;
            uint32_t* phw = (uint32_t*)&ph;
            uint32_t* plw = (uint32_t*)&pl;
            #pragma unroll
            for (int q = 0; q < 4; q++) {
                float w2[2], l2[2];
                #pragma unroll
                for (int e = 0; e < 2; e++) {
                    int j = c*8 + q*2 + e;
                    int m = mh*32 + j;
                    float s = fsrc_r + fd_s[m];
                    float w = (s >= 0.f) ? (Ap_r * Bp_s[m]) : (An_r * Bn_s[m]);
                    w = ((word >> j) & 1u) ? w : 0.f;
                    dsum += w;
                    float hf = __bfloat162float(__float2bfloat16(w));
                    w2[e] = w; l2[e] = w - hf;
                }
                phw[q] = pack_bf2(w2[0], w2[1]);
                plw[q] = pack_bf2(l2[0], l2[1]);
            }
            uint32_t so = (uint32_t)(r*72 + mh*32 + c*8)*2;
            *(uint4*)(smem + W_HI + so) = ph;
            *(uint4*)(smem + W_LO + so) = pl;
        }
        __syncthreads();
        // mma: acc += w @ vT^T  (3-term bf16 split)
        #pragma unroll
        for (int ko = 0; ko < 2; ko++) {
            uint32_t ah[8], al[8];
            ldsm_x4(ah+0, sb + W_HI + aOff + (ko*32)*2);
            ldsm_x4(ah+4, sb + W_HI + aOff + (ko*32+16)*2);
            ldsm_x4(al+0, sb + W_LO + aOff + (ko*32)*2);
            ldsm_x4(al+4, sb + W_LO + aOff + (ko*32+16)*2);
            #pragma unroll
            for (int dt = 0; dt < 8; dt++) {
                uint32_t bh[4], bl[4];
                ldsm_x4(bh, sb + V_HI + bOff + dt*1152 + ko*64);
                ldsm_x4(bl, sb + V_LO + bOff + dt*1152 + ko*64);
                mma_bf16(acc[dt], ah+0, bh+0);
                mma_bf16(acc[dt], ah+4, bh+2);
                mma_bf16(acc[dt], ah+0, bl+0);
                mma_bf16(acc[dt], ah+4, bl+2);
                mma_bf16(acc[dt], al+0, bh+0);
                mma_bf16(acc[dt], al+4, bh+2);
            }
        }
    }

    ds[mh*128 + r] = dsum;
    __syncthreads();

    int r0 = wid*16 + (lane >> 2);
    int r1 = r0 + 8;
    int cbase = (lane & 3)*2;
    if (partial) {
        if (t < 128) pden[(size_t)seg*NN + n0 + t] = ds[t] + ds[128 + t];
        float* p0 = pnum + ((size_t)seg*NN + n0 + r0)*64;
        float* p1 = pnum + ((size_t)seg*NN + n0 + r1)*64;
        #pragma unroll
        for (int dt = 0; dt < 8; dt++) {
            *(float2*)(p0 + dt*8 + cbase) = make_float2(acc[dt][0], acc[dt][1]);
            *(float2*)(p1 + dt*8 + cbase) = make_float2(acc[dt][2], acc[dt][3]);
        }
    } else {
        float inv0 = 1.0f / (ds[r0] + ds[128 + r0]);
        float inv1 = 1.0f / (ds[r1] + ds[128 + r1]);
        float* o0 = out + (size_t)(n0 + r0)*ldout + coloff;
        float* o1 = out + (size_t)(n0 + r1)*ldout + coloff;
        #pragma unroll
        for (int dt = 0; dt < 8; dt++) {
            float z0 = acc[dt][0]*inv0, z1 = acc[dt][1]*inv0;
            float z2 = acc[dt][2]*inv1, z3 = acc[dt][3]*inv1;
            if (applyElu) {
                z0 = (z0 > 0.f) ? z0 : expm1f(z0);
                z1 = (z1 > 0.f) ? z1 : expm1f(z1);
                z2 = (z2 > 0.f) ? z2 : expm1f(z2);
                z3 = (z3 > 0.f) ? z3 : expm1f(z3);
            }
            *(float2*)(o0 + dt*8 + cbase) = make_float2(z0, z1);
            *(float2*)(o1 + dt*8 + cbase) = make_float2(z2, z3);
        }
    }
}

// ------------- combine K-split partials -------------
__global__ void k_comb(const float* __restrict__ pnum, const float* __restrict__ pden,
                       float* __restrict__ h2)
{
    int gw = (blockIdx.x*blockDim.x + threadIdx.x) >> 5;
    int lane = threadIdx.x & 31;
    if (gw >= NN) return;
    float den = 0.f;
    #pragma unroll
    for (int s = 0; s < SPLIT; s++) den += pden[(size_t)s*NN + gw];
    float a0 = 0.f, a1 = 0.f;
    #pragma unroll
    for (int s = 0; s < SPLIT; s++) {
        const float* p = pnum + ((size_t)s*NN + gw)*64;
        a0 += p[lane]; a1 += p[lane+32];
    }
    float inv = 1.0f / den;
    h2[(size_t)gw*64 + lane]      = a0*inv;
    h2[(size_t)gw*64 + lane + 32] = a1*inv;
}

// ------------- ELU + row log_softmax over 64 features -------------
__global__ void k_final(const float* __restrict__ h2, float* __restrict__ out) {
    int gw = (blockIdx.x*blockDim.x + threadIdx.x) >> 5;
    int lane = threadIdx.x & 31;
    if (gw >= NN) return;
    const float* row = h2 + (size_t)gw*64;
    float z0 = row[lane], z1 = row[lane+32];
    z0 = (z0 > 0.f) ? z0 : expm1f(z0);
    z1 = (z1 > 0.f) ? z1 : expm1f(z1);
    float mx = fmaxf(z0, z1);
    #pragma unroll
    for (int o = 16; o; o >>= 1) mx = fmaxf(mx, __shfl_xor_sync(0xFFFFFFFFu, mx, o));
    float se = expf(z0 - mx) + expf(z1 - mx);
    #pragma unroll
    for (int o = 16; o; o >>= 1) se += __shfl_xor_sync(0xFFFFFFFFu, se, o);
    float lse = mx + logf(se);
    out[(size_t)gw*64 + lane]      = z0 - lse;
    out[(size_t)gw*64 + lane + 32] = z1 - lse;
}

extern "C" void kernel_launch(void* const* d_in, const int* in_sizes, int n_in,
                              void* d_out, int out_size)
{
    const float* x     = (const float*)d_in[0];
    const int*   adj   = (const int*)  d_in[1];
    const float* W     = (const float*)d_in[2];
    const float* asrc  = (const float*)d_in[3];
    const float* adst  = (const float*)d_in[4];
    const float* Wo    = (const float*)d_in[5];
    const float* aosrc = (const float*)d_in[6];
    const float* aodst = (const float*)d_in[7];
    float* out = (float*)d_out;

    void* sp = nullptr;  cudaGetSymbolAddress(&sp, g_scratch);
    void* bpv = nullptr; cudaGetSymbolAddress(&bpv, g_bits);
    void* bfv = nullptr; cudaGetSymbolAddress(&bfv, g_bf);
    float* S = (float*)sp;
    unsigned* bits = (unsigned*)bpv;
    __nv_bfloat16* BF = (__nv_bfloat16*)bfv;

    float* Wh   = S;
    float* hcat = Wh   + (size_t)NN*FF;
    float* Who  = hcat + (size_t)NN*FF;
    float* h2   = Who  + (size_t)NN*DD;
    float* fm   = h2   + (size_t)NN*DD;
    float* fsrc = fm;
    float* fdst = fm + 1*HH*NN;
    float* Ap   = fm + 2*HH*NN;
    float* An   = fm + 3*HH*NN;
    float* Bp   = fm + 4*HH*NN;
    float* Bn   = fm + 5*HH*NN;
    float* fo   = fm + 6*HH*NN;
    float* ofsrc = fo;        float* ofdst = fo + NN;
    float* oAp = fo + 2*NN;   float* oAn = fo + 3*NN;
    float* oBp = fo + 4*NN;   float* oBn = fo + 5*NN;
    float* pnum = fo + 6*NN;
    float* pden = pnum + (size_t)SPLIT*NN*DD;

    __nv_bfloat16* WhT_hi  = BF;
    __nv_bfloat16* WhT_lo  = WhT_hi + (size_t)NN*FF;
    __nv_bfloat16* WhoT_hi = WhT_lo + (size_t)NN*FF;
    __nv_bfloat16* WhoT_lo = WhoT_hi + (size_t)NN*DD;

    cudaFuncSetAttribute(k_attn_mma, cudaFuncAttributeMaxDynamicSharedMemorySize, SMEM_MMA);

    // 1) adj -> bitmask
    {
        long long threads = (long long)NN*(NN/32)*32;
        k_bits<<<(unsigned)((threads + 255)/256), 256>>>(adj, bits);
    }
    // 2) Wh = x @ W (all 8 heads, stored [n, h*64+d])
    k_gemm<<<dim3(NN/128, FF/64), 256>>>(x, FF, W, 0, 1, Wh, FF, FF);
    // 3) attention scalars + exp factorization (main heads)
    k_fexp<<<(HH*NN*32 + 255)/256, 256>>>(Wh, FF, asrc, adst,
                                          fsrc, fdst, Ap, An, Bp, Bn, HH);
    // 4) transpose+split Wh -> WhT hi/lo [h*64+d][NN]
    k_tsplit<<<dim3(NN/32, FF/32), 256>>>(Wh, FF, WhT_hi, WhT_lo);
    // 5) mma masked softmax-aggregation per head, ELU, write h_cat
    k_attn_mma<<<dim3(NN/128, HH, 1), 256, SMEM_MMA>>>(WhT_hi, WhT_lo,
        fsrc, fdst, Ap, An, Bp, Bn, bits, hcat, FF, 1, NN, nullptr, nullptr, 0);
    // 6) Who = h_cat @ W_o
    k_gemm<<<dim3(NN/128, DD/64), 256>>>(hcat, FF, Wo, DD, 0, Who, DD, FF);
    // 7) output-head attention scalars
    k_fexp<<<(NN*32 + 255)/256, 256>>>(Who, DD, aosrc, aodst,
                                       ofsrc, ofdst, oAp, oAn, oBp, oBn, 1);
    // 8) transpose+split Who -> WhoT hi/lo [d][NN]
    k_tsplit<<<dim3(NN/32, DD/32), 256>>>(Who, DD, WhoT_hi, WhoT_lo);
    // 9) output-head attention, 8-way K-split partials
    k_attn_mma<<<dim3(NN/128, 1, SPLIT), 256, SMEM_MMA>>>(WhoT_hi, WhoT_lo,
        ofsrc, ofdst, oAp, oAn, oBp, oBn, bits, nullptr, DD, 0, NN/SPLIT, pnum, pden, 1);
    // 10) combine partials -> h2
    k_comb<<<(NN*32 + 255)/256, 256>>>(pnum, pden, h2);
    // 11) ELU + log_softmax -> d_out
    k_final<<<(NN*32 + 255)/256, 256>>>(h2, out);
}

// round 4
// speedup vs baseline: 2.7540x; 1.2000x over previous
#include <cuda_runtime.h>
#include <cuda_bf16.h>
#include <cstdint>

#define NN 4096
#define FF 512
#define DD 64
#define HH 8
#define SPLIT 8

// ---------------------------------------------------------------- helpers
__device__ __forceinline__ void mma_bf16(float* d, const uint32_t* a, const uint32_t* b) {
    asm volatile("mma.sync.aligned.m16n8k16.row.col.f32.bf16.bf16.f32 "
        "{%0,%1,%2,%3}, {%4,%5,%6,%7}, {%8,%9}, {%0,%1,%2,%3};"
        : "+f"(d[0]), "+f"(d[1]), "+f"(d[2]), "+f"(d[3])
        : "r"(a[0]), "r"(a[1]), "r"(a[2]), "r"(a[3]), "r"(b[0]), "r"(b[1]));
}
__device__ __forceinline__ void ldsm_x4(uint32_t* r, uint32_t addr) {
    asm volatile("ldmatrix.sync.aligned.m8n8.x4.shared.b16 {%0,%1,%2,%3}, [%4];"
        : "=r"(r[0]), "=r"(r[1]), "=r"(r[2]), "=r"(r[3]) : "r"(addr));
}
__device__ __forceinline__ uint32_t smem_to_u32(const void* p) {
    uint32_t a;
    asm("{ .reg .u64 t; cvta.to.shared.u64 t, %1; cvt.u32.u64 %0, t; }" : "=r"(a) : "l"(p));
    return a;
}
__device__ __forceinline__ void cp16(uint32_t s, const void* g) {
    asm volatile("cp.async.cg.shared.global [%0], [%1], 16;" :: "r"(s), "l"(g));
}
#define CP_COMMIT() asm volatile("cp.async.commit_group;" ::: "memory")

__device__ __forceinline__ uint32_t pack_bf2(float a, float b) {
    __nv_bfloat162 p = __floats2bfloat162_rn(a, b);
    return *(uint32_t*)&p;
}
// hi/lo split of a pair into two packed bf16x2 regs
__device__ __forceinline__ void packsplit(float a, float b, uint32_t& hi, uint32_t& lo) {
    __nv_bfloat162 h = __floats2bfloat162_rn(a, b);
    hi = *(uint32_t*)&h;
    float ra = a - __bfloat162float(h.x);
    float rb = b - __bfloat162float(h.y);
    __nv_bfloat162 l = __floats2bfloat162_rn(ra, rb);
    lo = *(uint32_t*)&l;
}
__device__ __forceinline__ float wv(float4 s, float nfs, float APr, float ANr,
                                    unsigned bit, float& dsum) {
    bool p = s.x >= nfs;
    float w = (p ? APr : ANr) * (p ? s.y : s.z);
    w = bit ? w : 0.f;
    dsum += w;
    return w;
}

// ---------------------------------------------------------------- scratch
// floats: Wh(2M) Who(256K) h2(256K) fsrc/Ap/An main(3*HH*NN) pk main(HH*NN*4)
//         out-head 3*NN + pk_o NN*4 + pnum(SPLIT*NN*DD) + pden(SPLIT*NN)
#define SCR_FLOATS (NN*FF + NN*DD + NN*DD + 3*HH*NN + 4*HH*NN + 3*NN + 4*NN + SPLIT*NN*DD + SPLIT*NN)
__device__ __align__(16) float g_scratch[SCR_FLOATS];
__device__ unsigned g_bits[NN*(NN/32)];
// bf16: x_hi/lo(2*NN*FF) Wt(2*HH*FF*DD) WhT(2*NN*FF) hcat(2*NN*FF) Wot(2*FF*DD) WhoT(2*NN*DD)
#define BF_ELEMS (2*NN*FF + 2*HH*FF*DD + 2*NN*FF + 2*NN*FF + 2*FF*DD + 2*NN*DD)
__device__ __align__(16) __nv_bfloat16 g_bf[BF_ELEMS];

// ---------------- adj -> bitmask ----------------
__global__ void k_bits(const int* __restrict__ adj, unsigned* __restrict__ bits) {
    int gw = (blockIdx.x * blockDim.x + threadIdx.x) >> 5;
    int lane = threadIdx.x & 31;
    if (gw >= NN*(NN/32)) return;
    int v = adj[(size_t)gw*32 + lane];
    unsigned b = __ballot_sync(0xFFFFFFFFu, v > 0);
    if (lane == 0) bits[gw] = b;
}

// ---------------- elementwise hi/lo split ----------------
__global__ void k_split(const float* __restrict__ A,
                        __nv_bfloat16* __restrict__ Hi, __nv_bfloat16* __restrict__ Lo, int n4)
{
    int i = blockIdx.x*blockDim.x + threadIdx.x;
    if (i >= n4) return;
    float4 v = *(const float4*)(A + (size_t)i*4);
    uint32_t h0, l0, h1, l1;
    packsplit(v.x, v.y, h0, l0);
    packsplit(v.z, v.w, h1, l1);
    *(uint32_t*)(Hi + (size_t)i*4)     = h0;
    *(uint32_t*)(Hi + (size_t)i*4 + 2) = h1;
    *(uint32_t*)(Lo + (size_t)i*4)     = l0;
    *(uint32_t*)(Lo + (size_t)i*4 + 2) = l1;
}

// ---------------- batched transpose + split: A[z][R][C] -> T[z][C][R] ----------------
__global__ __launch_bounds__(256) void k_tsplitg(const float* __restrict__ A, int R, int C,
    __nv_bfloat16* __restrict__ Thi, __nv_bfloat16* __restrict__ Tlo)
{
    size_t zb = (size_t)blockIdx.z * R * C;
    A += zb; Thi += zb; Tlo += zb;
    __shared__ float tile[32][33];
    int n0 = blockIdx.x*32, c0 = blockIdx.y*32;
    int tx = threadIdx.x & 31, ty = threadIdx.x >> 5;
    #pragma unroll
    for (int i = 0; i < 4; i++) {
        int nr = ty*4 + i;
        tile[nr][tx] = A[(size_t)(n0+nr)*C + c0 + tx];
    }
    __syncthreads();
    #pragma unroll
    for (int i = 0; i < 4; i++) {
        int cr = ty*4 + i;
        float v = tile[tx][cr];
        __nv_bfloat16 h = __float2bfloat16(v);
        Thi[(size_t)(c0+cr)*R + n0 + tx] = h;
        Tlo[(size_t)(c0+cr)*R + n0 + tx] = __float2bfloat16(v - __bfloat162float(h));
    }
}

// ---------------- HMMA 3-term split GEMM: C[M][ldc] = A[M][K] @ B[ncols][K]^T ----------------
#define GA_H 0
#define GA_L 18432
#define GB_H 36864
#define GB_L 46080
#define SMEM_G 55296

__global__ __launch_bounds__(256) void k_gemm_tc(
    const __nv_bfloat16* __restrict__ Ah, const __nv_bfloat16* __restrict__ Al,
    const __nv_bfloat16* __restrict__ Bh, const __nv_bfloat16* __restrict__ Bl,
    float* __restrict__ C, int ldc, int K)
{
    extern __shared__ char smem[];
    uint32_t sb = smem_to_u32(smem);
    int t = threadIdx.x;
    int wid = t >> 5, lane = t & 31;
    int n0 = blockIdx.x*128, c0 = blockIdx.y*64;
    float acc[8][4];
    #pragma unroll
    for (int i = 0; i < 8; i++)
        #pragma unroll
        for (int j = 0; j < 4; j++) acc[i][j] = 0.f;

    int mrow = wid*16 + (lane&7) + ((lane>>3)&1)*8;
    uint32_t aOff = (uint32_t)(mrow*72 + (lane>>4)*8)*2;
    uint32_t bOff = (uint32_t)((lane&7)*72 + (lane>>3)*8)*2;

    for (int k0 = 0; k0 < K; k0 += 64) {
        __syncthreads();
        #pragma unroll
        for (int i = 0; i < 4; i++) {
            int idx = t + i*256;
            int row = idx >> 3, k16 = idx & 7;
            uint32_t so = (uint32_t)(row*144 + k16*16);
            *(uint4*)(smem + GA_H + so) = *(const uint4*)(Ah + (size_t)(n0+row)*K + k0 + k16*8);
            *(uint4*)(smem + GA_L + so) = *(const uint4*)(Al + (size_t)(n0+row)*K + k0 + k16*8);
        }
        #pragma unroll
        for (int i = 0; i < 2; i++) {
            int idx = t + i*256;
            int col = idx >> 3, k16 = idx & 7;
            uint32_t so = (uint32_t)(col*144 + k16*16);
            *(uint4*)(smem + GB_H + so) = *(const uint4*)(Bh + (size_t)(c0+col)*K + k0 + k16*8);
            *(uint4*)(smem + GB_L + so) = *(const uint4*)(Bl + (size_t)(c0+col)*K + k0 + k16*8);
        }
        __syncthreads();
        #pragma unroll
        for (int ko = 0; ko < 2; ko++) {
            uint32_t ah[8], al[8];
            ldsm_x4(ah+0, sb + GA_H + aOff + ko*64);
            ldsm_x4(ah+4, sb + GA_H + aOff + ko*64 + 32);
            ldsm_x4(al+0, sb + GA_L + aOff + ko*64);
            ldsm_x4(al+4, sb + GA_L + aOff + ko*64 + 32);
            #pragma unroll
            for (int dt = 0; dt < 8; dt++) {
                uint32_t bh[4], bl[4];
                ldsm_x4(bh, sb + GB_H + bOff + dt*1152 + ko*64);
                ldsm_x4(bl, sb + GB_L + bOff + dt*1152 + ko*64);
                mma_bf16(acc[dt], ah+0, bh+0);
                mma_bf16(acc[dt], ah+4, bh+2);
                mma_bf16(acc[dt], ah+0, bl+0);
                mma_bf16(acc[dt], ah+4, bl+2);
                mma_bf16(acc[dt], al+0, bh+0);
                mma_bf16(acc[dt], al+4, bh+2);
            }
        }
    }
    int r0 = wid*16 + (lane>>2), r1 = r0 + 8, c2 = (lane&3)*2;
    #pragma unroll
    for (int dt = 0; dt < 8; dt++) {
        *(float2*)(C + (size_t)(n0+r0)*ldc + c0 + dt*8 + c2) = make_float2(acc[dt][0], acc[dt][1]);
        *(float2*)(C + (size_t)(n0+r1)*ldc + c0 + dt*8 + c2) = make_float2(acc[dt][2], acc[dt][3]);
    }
}

// ------------- attention scalars + exp factorization (packed) -------------
__global__ void k_fexp(const float* __restrict__ Wh, int ld,
    const float* __restrict__ asrc, const float* __restrict__ adst,
    float* __restrict__ fsrc, float* __restrict__ Ap, float* __restrict__ An,
    float4* __restrict__ pk, int H)
{
    int gw = (blockIdx.x*blockDim.x + threadIdx.x) >> 5;
    int lane = threadIdx.x & 31;
    if (gw >= H*NN) return;
    int h = gw / NN, n = gw % NN;
    const float* row = Wh + (size_t)n*ld + h*64;
    float v0 = row[lane], v1 = row[lane+32];
    float fs = v0*asrc[h*64+lane] + v1*asrc[h*64+lane+32];
    float fd = v0*adst[h*64+lane] + v1*adst[h*64+lane+32];
    #pragma unroll
    for (int o = 16; o; o >>= 1) {
        fs += __shfl_xor_sync(0xFFFFFFFFu, fs, o);
        fd += __shfl_xor_sync(0xFFFFFFFFu, fd, o);
    }
    if (lane == 0) {
        fsrc[gw] = fs;
        Ap[gw] = expf(fs);
        An[gw] = expf(0.2f*fs);
        pk[gw] = make_float4(fd, expf(fd), expf(0.2f*fd), 0.f);
    }
}

// ------------- attn: w generated in A-fragment regs, cp.async double-buffered V -------------
#define VH_OFF 0
#define VL_OFF 9216
#define PK_OFF 18432
#define STAGE_B 19456
#define SMEM_ATT (2*STAGE_B)

__global__ __launch_bounds__(256) void k_attn_mma(
    const __nv_bfloat16* __restrict__ VT_hi,
    const __nv_bfloat16* __restrict__ VT_lo,
    const float* __restrict__ fsrc, const float* __restrict__ Ap, const float* __restrict__ An,
    const float4* __restrict__ pk,
    const unsigned* __restrict__ bits,
    __nv_bfloat16* __restrict__ out_hi, __nv_bfloat16* __restrict__ out_lo, int ldout,
    int mPerCta, float* __restrict__ pnum, float* __restrict__ pden, int partial)
{
    extern __shared__ char smem[];
    uint32_t sb = smem_to_u32(smem);
    int t = threadIdx.x;
    int wid = t >> 5, lane = t & 31;
    int head = blockIdx.y;
    int seg = blockIdx.z;
    int n0 = blockIdx.x * 128;
    int fbase = head * NN;
    int coloff = head * 64;
    int mStart = seg * mPerCta;
    int iters = mPerCta / 64;

    int qr = lane >> 2;
    int c2 = (lane & 3) * 2;
    int r0 = wid*16 + qr;
    int r1 = r0 + 8;

    float nfs0 = -fsrc[fbase + n0 + r0];
    float nfs1 = -fsrc[fbase + n0 + r1];
    float Ap0 = Ap[fbase + n0 + r0], Ap1 = Ap[fbase + n0 + r1];
    float An0 = An[fbase + n0 + r0], An1 = An[fbase + n0 + r1];
    const unsigned* brow0 = bits + (size_t)(n0 + r0)*(NN/32);
    const unsigned* brow1 = bits + (size_t)(n0 + r1)*(NN/32);

    float acc[8][4];
    #pragma unroll
    for (int i = 0; i < 8; i++)
        #pragma unroll
        for (int j = 0; j < 4; j++) acc[i][j] = 0.f;
    float ds0 = 0.f, ds1 = 0.f;

    auto stage = [&](int it) {
        uint32_t dst = sb + (uint32_t)(it & 1)*STAGE_B;
        int m0 = mStart + it*64;
        #pragma unroll
        for (int i = 0; i < 2; i++) {
            int idx = t + i*256;
            int d = idx >> 3, k16 = idx & 7;
            cp16(dst + VH_OFF + d*144 + k16*16, VT_hi + (size_t)(coloff + d)*NN + m0 + k16*8);
            cp16(dst + VL_OFF + d*144 + k16*16, VT_lo + (size_t)(coloff + d)*NN + m0 + k16*8);
        }
        if (t < 64) cp16(dst + PK_OFF + t*16, pk + fbase + m0 + t);
        CP_COMMIT();
    };

    stage(0);
    uint32_t bOff = (uint32_t)((lane & 7)*72 + (lane >> 3)*8)*2;

    for (int it = 0; it < iters; it++) {
        if (it + 1 < iters) {
            stage(it + 1);
            asm volatile("cp.async.wait_group 1;" ::: "memory");
        } else {
            asm volatile("cp.async.wait_group 0;" ::: "memory");
        }
        __syncthreads();

        uint32_t sbuf = sb + (uint32_t)(it & 1)*STAGE_B;
        const float4* pks = (const float4*)(smem + (it & 1)*STAGE_B + PK_OFF);
        int m0 = mStart + it*64;
        int wbase = m0 >> 5;
        unsigned b00 = brow0[wbase], b01 = brow0[wbase+1];
        unsigned b10 = brow1[wbase], b11 = brow1[wbase+1];

        uint32_t ah[4][4], al[4][4];
        #pragma unroll
        for (int kc = 0; kc < 4; kc++) {
            int mA = kc*16 + c2;
            int mB = mA + 8;
            float4 sA0 = pks[mA], sA1 = pks[mA+1];
            float4 sB0 = pks[mB], sB1 = pks[mB+1];
            unsigned w0 = (kc < 2) ? b00 : b01;
            unsigned w1 = (kc < 2) ? b10 : b11;
            int jA = mA & 31, jB = mB & 31;
            float wA0r0 = wv(sA0, nfs0, Ap0, An0, (w0 >> jA) & 1u, ds0);
            float wA1r0 = wv(sA1, nfs0, Ap0, An0, (w0 >> (jA+1)) & 1u, ds0);
            float wA0r1 = wv(sA0, nfs1, Ap1, An1, (w1 >> jA) & 1u, ds1);
            float wA1r1 = wv(sA1, nfs1, Ap1, An1, (w1 >> (jA+1)) & 1u, ds1);
            float wB0r0 = wv(sB0, nfs0, Ap0, An0, (w0 >> jB) & 1u, ds0);
            float wB1r0 = wv(sB1, nfs0, Ap0, An0, (w0 >> (jB+1)) & 1u, ds0);
            float wB0r1 = wv(sB0, nfs1, Ap1, An1, (w1 >> jB) & 1u, ds1);
            float wB1r1 = wv(sB1, nfs1, Ap1, An1, (w1 >> (jB+1)) & 1u, ds1);
            packsplit(wA0r0, wA1r0, ah[kc][0], al[kc][0]);
            packsplit(wA0r1, wA1r1, ah[kc][1], al[kc][1]);
            packsplit(wB0r0, wB1r0, ah[kc][2], al[kc][2]);
            packsplit(wB0r1, wB1r1, ah[kc][3], al[kc][3]);
        }

        #pragma unroll
        for (int ko = 0; ko < 2; ko++) {
            #pragma unroll
            for (int dt = 0; dt < 8; dt++) {
                uint32_t bh[4], bl[4];
                ldsm_x4(bh, sbuf + VH_OFF + bOff + dt*1152 + ko*64);
                ldsm_x4(bl, sbuf + VL_OFF + bOff + dt*1152 + ko*64);
                mma_bf16(acc[dt], ah[2*ko],   bh+0);
                mma_bf16(acc[dt], ah[2*ko+1], bh+2);
                mma_bf16(acc[dt], ah[2*ko],   bl+0);
                mma_bf16(acc[dt], ah[2*ko+1], bl+2);
                mma_bf16(acc[dt], al[2*ko],   bh+0);
                mma_bf16(acc[dt], al[2*ko+1], bh+2);
            }
        }
        __syncthreads();
    }

    // denominator: reduce over the 4 lanes of the quad (each covered 16 of 64 m per row)
    ds0 += __shfl_xor_sync(0xFFFFFFFFu, ds0, 1);
    ds0 += __shfl_xor_sync(0xFFFFFFFFu, ds0, 2);
    ds1 += __shfl_xor_sync(0xFFFFFFFFu, ds1, 1);
    ds1 += __shfl_xor_sync(0xFFFFFFFFu, ds1, 2);

    if (partial) {
        if ((lane & 3) == 0) {
            pden[(size_t)seg*NN + n0 + r0] = ds0;
            pden[(size_t)seg*NN + n0 + r1] = ds1;
        }
        float* p0 = pnum + ((size_t)seg*NN + n0 + r0)*64;
        float* p1 = pnum + ((size_t)seg*NN + n0 + r1)*64;
        #pragma unroll
        for (int dt = 0; dt < 8; dt++) {
            *(float2*)(p0 + dt*8 + c2) = make_float2(acc[dt][0], acc[dt][1]);
            *(float2*)(p1 + dt*8 + c2) = make_float2(acc[dt][2], acc[dt][3]);
        }
    } else {
        float inv0 = 1.0f / ds0, inv1 = 1.0f / ds1;
        #pragma unroll
        for (int dt = 0; dt < 8; dt++) {
            float z0 = acc[dt][0]*inv0, z1 = acc[dt][1]*inv0;
            float z2 = acc[dt][2]*inv1, z3 = acc[dt][3]*inv1;
            z0 = (z0 > 0.f) ? z0 : expm1f(z0);
            z1 = (z1 > 0.f) ? z1 : expm1f(z1);
            z2 = (z2 > 0.f) ? z2 : expm1f(z2);
            z3 = (z3 > 0.f) ? z3 : expm1f(z3);
            uint32_t h0, l0, h1, l1;
            packsplit(z0, z1, h0, l0);
            packsplit(z2, z3, h1, l1);
            size_t o0 = (size_t)(n0+r0)*ldout + coloff + dt*8 + c2;
            size_t o1 = (size_t)(n0+r1)*ldout + coloff + dt*8 + c2;
            *(uint32_t*)(out_hi + o0) = h0;
            *(uint32_t*)(out_lo + o0) = l0;
            *(uint32_t*)(out_hi + o1) = h1;
            *(uint32_t*)(out_lo + o1) = l1;
        }
    }
}

// ------------- combine K-split partials -------------
__global__ void k_comb(const float* __restrict__ pnum, const float* __restrict__ pden,
                       float* __restrict__ h2)
{
    int gw = (blockIdx.x*blockDim.x + threadIdx.x) >> 5;
    int lane = threadIdx.x & 31;
    if (gw >= NN) return;
    float den = 0.f;
    #pragma unroll
    for (int s = 0; s < SPLIT; s++) den += pden[(size_t)s*NN + gw];
    float a0 = 0.f, a1 = 0.f;
    #pragma unroll
    for (int s = 0; s < SPLIT; s++) {
        const float* p = pnum + ((size_t)s*NN + gw)*64;
        a0 += p[lane]; a1 += p[lane+32];
    }
    float inv = 1.0f / den;
    h2[(size_t)gw*64 + lane]      = a0*inv;
    h2[(size_t)gw*64 + lane + 32] = a1*inv;
}

// ------------- ELU + row log_softmax -------------
__global__ void k_final(const float* __restrict__ h2, float* __restrict__ out) {
    int gw = (blockIdx.x*blockDim.x + threadIdx.x) >> 5;
    int lane = threadIdx.x & 31;
    if (gw >= NN) return;
    const float* row = h2 + (size_t)gw*64;
    float z0 = row[lane], z1 = row[lane+32];
    z0 = (z0 > 0.f) ? z0 : expm1f(z0);
    z1 = (z1 > 0.f) ? z1 : expm1f(z1);
    float mx = fmaxf(z0, z1);
    #pragma unroll
    for (int o = 16; o; o >>= 1) mx = fmaxf(mx, __shfl_xor_sync(0xFFFFFFFFu, mx, o));
    float se = expf(z0 - mx) + expf(z1 - mx);
    #pragma unroll
    for (int o = 16; o; o >>= 1) se += __shfl_xor_sync(0xFFFFFFFFu, se, o);
    float lse = mx + logf(se);
    out[(size_t)gw*64 + lane]      = z0 - lse;
    out[(size_t)gw*64 + lane + 32] = z1 - lse;
}

extern "C" void kernel_launch(void* const* d_in, const int* in_sizes, int n_in,
                              void* d_out, int out_size)
{
    const float* x     = (const float*)d_in[0];
    const int*   adj   = (const int*)  d_in[1];
    const float* W     = (const float*)d_in[2];
    const float* asrc  = (const float*)d_in[3];
    const float* adst  = (const float*)d_in[4];
    const float* Wo    = (const float*)d_in[5];
    const float* aosrc = (const float*)d_in[6];
    const float* aodst = (const float*)d_in[7];
    float* out = (float*)d_out;

    void* sp = nullptr;  cudaGetSymbolAddress(&sp, g_scratch);
    void* bpv = nullptr; cudaGetSymbolAddress(&bpv, g_bits);
    void* bfv = nullptr; cudaGetSymbolAddress(&bfv, g_bf);
    float* S = (float*)sp;
    unsigned* bits = (unsigned*)bpv;
    __nv_bfloat16* BF = (__nv_bfloat16*)bfv;

    float* Wh    = S;                                  // NN*FF
    float* Who   = Wh  + (size_t)NN*FF;                // NN*DD
    float* h2    = Who + (size_t)NN*DD;                // NN*DD
    float* fsrcM = h2  + (size_t)NN*DD;                // HH*NN
    float* ApM   = fsrcM + (size_t)HH*NN;
    float* AnM   = ApM   + (size_t)HH*NN;
    float4* pkM  = (float4*)(AnM + (size_t)HH*NN);     // HH*NN float4
    float* fsrcO = (float*)(pkM + (size_t)HH*NN);      // NN
    float* ApO   = fsrcO + NN;
    float* AnO   = ApO + NN;
    float4* pkO  = (float4*)(AnO + NN);                // NN float4
    float* pnum  = (float*)(pkO + NN);                 // SPLIT*NN*DD
    float* pden  = pnum + (size_t)SPLIT*NN*DD;         // SPLIT*NN

    __nv_bfloat16* x_hi   = BF;
    __nv_bfloat16* x_lo   = x_hi   + (size_t)NN*FF;
    __nv_bfloat16* Wt_hi  = x_lo   + (size_t)NN*FF;
    __nv_bfloat16* Wt_lo  = Wt_hi  + (size_t)HH*FF*DD;
    __nv_bfloat16* WhT_hi = Wt_lo  + (size_t)HH*FF*DD;
    __nv_bfloat16* WhT_lo = WhT_hi + (size_t)NN*FF;
    __nv_bfloat16* hc_hi  = WhT_lo + (size_t)NN*FF;
    __nv_bfloat16* hc_lo  = hc_hi  + (size_t)NN*FF;
    __nv_bfloat16* Wot_hi = hc_lo  + (size_t)NN*FF;
    __nv_bfloat16* Wot_lo = Wot_hi + (size_t)FF*DD;
    __nv_bfloat16* WoT_hi = Wot_lo + (size_t)FF*DD;
    __nv_bfloat16* WoT_lo = WoT_hi + (size_t)NN*DD;

    cudaFuncSetAttribute(k_gemm_tc, cudaFuncAttributeMaxDynamicSharedMemorySize, SMEM_G);
    cudaFuncSetAttribute(k_attn_mma, cudaFuncAttributeMaxDynamicSharedMemorySize, SMEM_ATT);

    // 1) adj -> bitmask
    {
        long long threads = (long long)NN*(NN/32)*32;
        k_bits<<<(unsigned)((threads + 255)/256), 256>>>(adj, bits);
    }
    // 2) split x; transpose+split W (per head)
    k_split<<<(NN*FF/4 + 255)/256, 256>>>(x, x_hi, x_lo, NN*FF/4);
    k_tsplitg<<<dim3(FF/32, DD/32, HH), 256>>>(W, FF, DD, Wt_hi, Wt_lo);
    // 3) Wh = x @ W (HMMA)
    k_gemm_tc<<<dim3(NN/128, FF/64), 256, SMEM_G>>>(x_hi, x_lo, Wt_hi, Wt_lo, Wh, FF, FF);
    // 4) attention scalars (main)
    k_fexp<<<(HH*NN*32 + 255)/256, 256>>>(Wh, FF, asrc, adst, fsrcM, ApM, AnM, pkM, HH);
    // 5) transpose+split Wh -> WhT
    k_tsplitg<<<dim3(NN/32, FF/32, 1), 256>>>(Wh, NN, FF, WhT_hi, WhT_lo);
    // 6) main attention -> hcat hi/lo (ELU applied)
    k_attn_mma<<<dim3(NN/128, HH, 1), 256, SMEM_ATT>>>(WhT_hi, WhT_lo,
        fsrcM, ApM, AnM, pkM, bits, hc_hi, hc_lo, FF, NN, nullptr, nullptr, 0);
    // 7) transpose+split Wo; Who = hcat @ Wo (HMMA)
    k_tsplitg<<<dim3(FF/32, DD/32, 1), 256>>>(Wo, FF, DD, Wot_hi, Wot_lo);
    k_gemm_tc<<<dim3(NN/128, DD/64), 256, SMEM_G>>>(hc_hi, hc_lo, Wot_hi, Wot_lo, Who, DD, FF);
    // 8) out-head scalars
    k_fexp<<<(NN*32 + 255)/256, 256>>>(Who, DD, aosrc, aodst, fsrcO, ApO, AnO, pkO, 1);
    // 9) transpose+split Who
    k_tsplitg<<<dim3(NN/32, DD/32, 1), 256>>>(Who, NN, DD, WoT_hi, WoT_lo);
    // 10) out-head attention, 8-way K-split
    k_attn_mma<<<dim3(NN/128, 1, SPLIT), 256, SMEM_ATT>>>(WoT_hi, WoT_lo,
        fsrcO, ApO, AnO, pkO, bits, nullptr, nullptr, DD, NN/SPLIT, pnum, pden, 1);
    // 11) combine + final
    k_comb<<<(NN*32 + 255)/256, 256>>>(pnum, pden, h2);
    k_final<<<(NN*32 + 255)/256, 256>>>(h2, out);
}

// round 5
// speedup vs baseline: 2.8802x; 1.0458x over previous
#include <cuda_runtime.h>
#include <cuda_bf16.h>
#include <cstdint>

#define NN 4096
#define FF 512
#define DD 64
#define HH 8
#define SPLIT 8

// ---------------------------------------------------------------- helpers
__device__ __forceinline__ void mma_bf16(float* d, const uint32_t* a, const uint32_t* b) {
    asm volatile("mma.sync.aligned.m16n8k16.row.col.f32.bf16.bf16.f32 "
        "{%0,%1,%2,%3}, {%4,%5,%6,%7}, {%8,%9}, {%0,%1,%2,%3};"
        : "+f"(d[0]), "+f"(d[1]), "+f"(d[2]), "+f"(d[3])
        : "r"(a[0]), "r"(a[1]), "r"(a[2]), "r"(a[3]), "r"(b[0]), "r"(b[1]));
}
__device__ __forceinline__ void ldsm_x4(uint32_t* r, uint32_t addr) {
    asm volatile("ldmatrix.sync.aligned.m8n8.x4.shared.b16 {%0,%1,%2,%3}, [%4];"
        : "=r"(r[0]), "=r"(r[1]), "=r"(r[2]), "=r"(r[3]) : "r"(addr));
}
__device__ __forceinline__ uint32_t smem_to_u32(const void* p) {
    uint32_t a;
    asm("{ .reg .u64 t; cvta.to.shared.u64 t, %1; cvt.u32.u64 %0, t; }" : "=r"(a) : "l"(p));
    return a;
}
__device__ __forceinline__ void cp16(uint32_t s, const void* g) {
    asm volatile("cp.async.cg.shared.global [%0], [%1], 16;" :: "r"(s), "l"(g));
}
#define CP_COMMIT() asm volatile("cp.async.commit_group;" ::: "memory")
#define CP_WAIT(N)  asm volatile("cp.async.wait_group %0;" :: "n"(N) : "memory")

__device__ __forceinline__ void packsplit(float a, float b, uint32_t& hi, uint32_t& lo) {
    __nv_bfloat162 h = __floats2bfloat162_rn(a, b);
    hi = *(uint32_t*)&h;
    float ra = a - __bfloat162float(h.x);
    float rb = b - __bfloat162float(h.y);
    __nv_bfloat162 l = __floats2bfloat162_rn(ra, rb);
    lo = *(uint32_t*)&l;
}
__device__ __forceinline__ float wv(float4 s, float nfs, float APr, float ANr,
                                    unsigned bit, float& dsum) {
    bool p = s.x >= nfs;
    float w = (p ? APr : ANr) * (p ? s.y : s.z);
    w = bit ? w : 0.f;
    dsum += w;
    return w;
}

// ---------------------------------------------------------------- scratch
#define SCR_FLOATS (NN*FF + NN*DD + NN*DD + 3*HH*NN + 4*HH*NN + 3*NN + 4*NN + SPLIT*NN*DD + SPLIT*NN)
__device__ __align__(16) float g_scratch[SCR_FLOATS];
__device__ unsigned g_bits[NN*(NN/32)];
#define BF_ELEMS (2*NN*FF + 2*HH*FF*DD + 2*NN*FF + 2*NN*FF + 2*FF*DD + 2*NN*DD)
__device__ __align__(16) __nv_bfloat16 g_bf[BF_ELEMS];

// ---------------- adj -> bitmask ----------------
__global__ void k_bits(const int* __restrict__ adj, unsigned* __restrict__ bits) {
    int gw = (blockIdx.x * blockDim.x + threadIdx.x) >> 5;
    int lane = threadIdx.x & 31;
    if (gw >= NN*(NN/32)) return;
    int v = adj[(size_t)gw*32 + lane];
    unsigned b = __ballot_sync(0xFFFFFFFFu, v > 0);
    if (lane == 0) bits[gw] = b;
}

// ---------------- elementwise hi/lo split ----------------
__global__ void k_split(const float* __restrict__ A,
                        __nv_bfloat16* __restrict__ Hi, __nv_bfloat16* __restrict__ Lo, int n4)
{
    int i = blockIdx.x*blockDim.x + threadIdx.x;
    if (i >= n4) return;
    float4 v = *(const float4*)(A + (size_t)i*4);
    uint32_t h0, l0, h1, l1;
    packsplit(v.x, v.y, h0, l0);
    packsplit(v.z, v.w, h1, l1);
    *(uint32_t*)(Hi + (size_t)i*4)     = h0;
    *(uint32_t*)(Hi + (size_t)i*4 + 2) = h1;
    *(uint32_t*)(Lo + (size_t)i*4)     = l0;
    *(uint32_t*)(Lo + (size_t)i*4 + 2) = l1;
}

// ---------------- batched transpose + split: A[z][R][C] -> T[z][C][R] ----------------
__global__ __launch_bounds__(256) void k_tsplitg(const float* __restrict__ A, int R, int C,
    __nv_bfloat16* __restrict__ Thi, __nv_bfloat16* __restrict__ Tlo)
{
    size_t zb = (size_t)blockIdx.z * R * C;
    A += zb; Thi += zb; Tlo += zb;
    __shared__ float tile[32][33];
    int n0 = blockIdx.x*32, c0 = blockIdx.y*32;
    int tx = threadIdx.x & 31, ty = threadIdx.x >> 5;
    #pragma unroll
    for (int i = 0; i < 4; i++) {
        int nr = ty*4 + i;
        tile[nr][tx] = A[(size_t)(n0+nr)*C + c0 + tx];
    }
    __syncthreads();
    #pragma unroll
    for (int i = 0; i < 4; i++) {
        int cr = ty*4 + i;
        float v = tile[tx][cr];
        __nv_bfloat16 h = __float2bfloat16(v);
        Thi[(size_t)(c0+cr)*R + n0 + tx] = h;
        Tlo[(size_t)(c0+cr)*R + n0 + tx] = __float2bfloat16(v - __bfloat162float(h));
    }
}

// ---------------- HMMA 3-term split GEMM, cp.async 2-stage pipeline ----------------
#define G_AH 0
#define G_AL 18432
#define G_BH 36864
#define G_BL 46080
#define G_STAGE 55296
#define SMEM_G (2*G_STAGE)

__global__ __launch_bounds__(256, 2) void k_gemm_tc(
    const __nv_bfloat16* __restrict__ Ah, const __nv_bfloat16* __restrict__ Al,
    const __nv_bfloat16* __restrict__ Bh, const __nv_bfloat16* __restrict__ Bl,
    float* __restrict__ C, int ldc, int K)
{
    extern __shared__ char smem[];
    uint32_t sb = smem_to_u32(smem);
    int t = threadIdx.x;
    int wid = t >> 5, lane = t & 31;
    int n0 = blockIdx.x*128, c0 = blockIdx.y*64;
    float acc[8][4];
    #pragma unroll
    for (int i = 0; i < 8; i++)
        #pragma unroll
        for (int j = 0; j < 4; j++) acc[i][j] = 0.f;

    int mrow = wid*16 + (lane&7) + ((lane>>3)&1)*8;
    uint32_t aOff = (uint32_t)(mrow*72 + (lane>>4)*8)*2;
    uint32_t bOff = (uint32_t)((lane&7)*72 + (lane>>3)*8)*2;

    int chunks = K/64;
    auto stage = [&](int kc) {
        uint32_t dst = sb + (uint32_t)(kc & 1)*G_STAGE;
        int k0 = kc*64;
        #pragma unroll
        for (int i = 0; i < 4; i++) {
            int idx = t + i*256;
            int row = idx >> 3, k16 = idx & 7;
            cp16(dst + G_AH + row*144 + k16*16, Ah + (size_t)(n0+row)*K + k0 + k16*8);
            cp16(dst + G_AL + row*144 + k16*16, Al + (size_t)(n0+row)*K + k0 + k16*8);
        }
        #pragma unroll
        for (int i = 0; i < 2; i++) {
            int idx = t + i*256;
            int col = idx >> 3, k16 = idx & 7;
            cp16(dst + G_BH + col*144 + k16*16, Bh + (size_t)(c0+col)*K + k0 + k16*8);
            cp16(dst + G_BL + col*144 + k16*16, Bl + (size_t)(c0+col)*K + k0 + k16*8);
        }
        CP_COMMIT();
    };

    stage(0);
    for (int kc = 0; kc < chunks; kc++) {
        if (kc + 1 < chunks) { stage(kc + 1); CP_WAIT(1); }
        else                 { CP_WAIT(0); }
        __syncthreads();
        uint32_t sbuf = sb + (uint32_t)(kc & 1)*G_STAGE;
        #pragma unroll
        for (int ko = 0; ko < 2; ko++) {
            uint32_t ah[8], al[8];
            ldsm_x4(ah+0, sbuf + G_AH + aOff + ko*64);
            ldsm_x4(ah+4, sbuf + G_AH + aOff + ko*64 + 32);
            ldsm_x4(al+0, sbuf + G_AL + aOff + ko*64);
            ldsm_x4(al+4, sbuf + G_AL + aOff + ko*64 + 32);
            #pragma unroll
            for (int dt = 0; dt < 8; dt++) {
                uint32_t bh[4], bl[4];
                ldsm_x4(bh, sbuf + G_BH + bOff + dt*1152 + ko*64);
                ldsm_x4(bl, sbuf + G_BL + bOff + dt*1152 + ko*64);
                mma_bf16(acc[dt], ah+0, bh+0);
                mma_bf16(acc[dt], ah+4, bh+2);
                mma_bf16(acc[dt], ah+0, bl+0);
                mma_bf16(acc[dt], ah+4, bl+2);
                mma_bf16(acc[dt], al+0, bh+0);
                mma_bf16(acc[dt], al+4, bh+2);
            }
        }
        __syncthreads();
    }
    int r0 = wid*16 + (lane>>2), r1 = r0 + 8, c2 = (lane&3)*2;
    #pragma unroll
    for (int dt = 0; dt < 8; dt++) {
        *(float2*)(C + (size_t)(n0+r0)*ldc + c0 + dt*8 + c2) = make_float2(acc[dt][0], acc[dt][1]);
        *(float2*)(C + (size_t)(n0+r1)*ldc + c0 + dt*8 + c2) = make_float2(acc[dt][2], acc[dt][3]);
    }
}

// ------------- attention scalars + exp factorization (packed) -------------
__global__ void k_fexp(const float* __restrict__ Wh, int ld,
    const float* __restrict__ asrc, const float* __restrict__ adst,
    float* __restrict__ fsrc, float* __restrict__ Ap, float* __restrict__ An,
    float4* __restrict__ pk, int H)
{
    int gw = (blockIdx.x*blockDim.x + threadIdx.x) >> 5;
    int lane = threadIdx.x & 31;
    if (gw >= H*NN) return;
    int h = gw / NN, n = gw % NN;
    const float* row = Wh + (size_t)n*ld + h*64;
    float v0 = row[lane], v1 = row[lane+32];
    float fs = v0*asrc[h*64+lane] + v1*asrc[h*64+lane+32];
    float fd = v0*adst[h*64+lane] + v1*adst[h*64+lane+32];
    #pragma unroll
    for (int o = 16; o; o >>= 1) {
        fs += __shfl_xor_sync(0xFFFFFFFFu, fs, o);
        fd += __shfl_xor_sync(0xFFFFFFFFu, fd, o);
    }
    if (lane == 0) {
        fsrc[gw] = fs;
        Ap[gw] = expf(fs);
        An[gw] = expf(0.2f*fs);
        pk[gw] = make_float4(fd, expf(fd), expf(0.2f*fd), 0.f);
    }
}

// ------------- attn: w in A-fragment regs, cp.async 3-stage V pipeline -------------
#define VH_OFF 0
#define VL_OFF 9216
#define PK_OFF 18432
#define STAGE_B 19456
#define SMEM_ATT (3*STAGE_B)

__global__ __launch_bounds__(256, 2) void k_attn_mma(
    const __nv_bfloat16* __restrict__ VT_hi,
    const __nv_bfloat16* __restrict__ VT_lo,
    const float* __restrict__ fsrc, const float* __restrict__ Ap, const float* __restrict__ An,
    const float4* __restrict__ pk,
    const unsigned* __restrict__ bits,
    __nv_bfloat16* __restrict__ out_hi, __nv_bfloat16* __restrict__ out_lo, int ldout,
    int mPerCta, float* __restrict__ pnum, float* __restrict__ pden, int partial)
{
    extern __shared__ char smem[];
    uint32_t sb = smem_to_u32(smem);
    int t = threadIdx.x;
    int wid = t >> 5, lane = t & 31;
    int head = blockIdx.y;
    int seg = blockIdx.z;
    int n0 = blockIdx.x * 128;
    int fbase = head * NN;
    int coloff = head * 64;
    int mStart = seg * mPerCta;
    int iters = mPerCta / 64;

    int qr = lane >> 2;
    int c2 = (lane & 3) * 2;
    int r0 = wid*16 + qr;
    int r1 = r0 + 8;

    float nfs0 = -fsrc[fbase + n0 + r0];
    float nfs1 = -fsrc[fbase + n0 + r1];
    float Ap0 = Ap[fbase + n0 + r0], Ap1 = Ap[fbase + n0 + r1];
    float An0 = An[fbase + n0 + r0], An1 = An[fbase + n0 + r1];
    const unsigned* brow0 = bits + (size_t)(n0 + r0)*(NN/32);
    const unsigned* brow1 = bits + (size_t)(n0 + r1)*(NN/32);

    float acc[8][4];
    #pragma unroll
    for (int i = 0; i < 8; i++)
        #pragma unroll
        for (int j = 0; j < 4; j++) acc[i][j] = 0.f;
    float ds0 = 0.f, ds1 = 0.f;

    auto stage = [&](int it) {
        uint32_t dst = sb + (uint32_t)(it % 3)*STAGE_B;
        int m0 = mStart + it*64;
        #pragma unroll
        for (int i = 0; i < 2; i++) {
            int idx = t + i*256;
            int d = idx >> 3, k16 = idx & 7;
            cp16(dst + VH_OFF + d*144 + k16*16, VT_hi + (size_t)(coloff + d)*NN + m0 + k16*8);
            cp16(dst + VL_OFF + d*144 + k16*16, VT_lo + (size_t)(coloff + d)*NN + m0 + k16*8);
        }
        if (t < 64) cp16(dst + PK_OFF + t*16, pk + fbase + m0 + t);
        CP_COMMIT();
    };

    stage(0);
    if (iters > 1) stage(1);
    uint32_t bOff = (uint32_t)((lane & 7)*72 + (lane >> 3)*8)*2;

    for (int it = 0; it < iters; it++) {
        if (it + 2 < iters)      { stage(it + 2); CP_WAIT(2); }
        else if (it + 1 < iters) { CP_WAIT(1); }
        else                     { CP_WAIT(0); }
        __syncthreads();

        int buf = it % 3;
        uint32_t sbuf = sb + (uint32_t)buf*STAGE_B;
        const float4* pks = (const float4*)(smem + buf*STAGE_B + PK_OFF);
        int m0 = mStart + it*64;
        int wbase = m0 >> 5;
        unsigned b00 = brow0[wbase], b01 = brow0[wbase+1];
        unsigned b10 = brow1[wbase], b11 = brow1[wbase+1];

        uint32_t ah[4][4], al[4][4];
        #pragma unroll
        for (int kc = 0; kc < 4; kc++) {
            int mA = kc*16 + c2;
            int mB = mA + 8;
            float4 sA0 = pks[mA], sA1 = pks[mA+1];
            float4 sB0 = pks[mB], sB1 = pks[mB+1];
            unsigned w0 = (kc < 2) ? b00 : b01;
            unsigned w1 = (kc < 2) ? b10 : b11;
            int jA = mA & 31, jB = mB & 31;
            float wA0r0 = wv(sA0, nfs0, Ap0, An0, (w0 >> jA) & 1u, ds0);
            float wA1r0 = wv(sA1, nfs0, Ap0, An0, (w0 >> (jA+1)) & 1u, ds0);
            float wA0r1 = wv(sA0, nfs1, Ap1, An1, (w1 >> jA) & 1u, ds1);
            float wA1r1 = wv(sA1, nfs1, Ap1, An1, (w1 >> (jA+1)) & 1u, ds1);
            float wB0r0 = wv(sB0, nfs0, Ap0, An0, (w0 >> jB) & 1u, ds0);
            float wB1r0 = wv(sB1, nfs0, Ap0, An0, (w0 >> (jB+1)) & 1u, ds0);
            float wB0r1 = wv(sB0, nfs1, Ap1, An1, (w1 >> jB) & 1u, ds1);
            float wB1r1 = wv(sB1, nfs1, Ap1, An1, (w1 >> (jB+1)) & 1u, ds1);
            packsplit(wA0r0, wA1r0, ah[kc][0], al[kc][0]);
            packsplit(wA0r1, wA1r1, ah[kc][1], al[kc][1]);
            packsplit(wB0r0, wB1r0, ah[kc][2], al[kc][2]);
            packsplit(wB0r1, wB1r1, ah[kc][3], al[kc][3]);
        }

        #pragma unroll
        for (int ko = 0; ko < 2; ko++) {
            #pragma unroll
            for (int dt = 0; dt < 8; dt++) {
                uint32_t bh[4], bl[4];
                ldsm_x4(bh, sbuf + VH_OFF + bOff + dt*1152 + ko*64);
                ldsm_x4(bl, sbuf + VL_OFF + bOff + dt*1152 + ko*64);
                mma_bf16(acc[dt], ah[2*ko],   bh+0);
                mma_bf16(acc[dt], ah[2*ko+1], bh+2);
                mma_bf16(acc[dt], ah[2*ko],   bl+0);
                mma_bf16(acc[dt], ah[2*ko+1], bl+2);
                mma_bf16(acc[dt], al[2*ko],   bh+0);
                mma_bf16(acc[dt], al[2*ko+1], bh+2);
            }
        }
        __syncthreads();
    }

    ds0 += __shfl_xor_sync(0xFFFFFFFFu, ds0, 1);
    ds0 += __shfl_xor_sync(0xFFFFFFFFu, ds0, 2);
    ds1 += __shfl_xor_sync(0xFFFFFFFFu, ds1, 1);
    ds1 += __shfl_xor_sync(0xFFFFFFFFu, ds1, 2);

    if (partial) {
        if ((lane & 3) == 0) {
            pden[(size_t)seg*NN + n0 + r0] = ds0;
            pden[(size_t)seg*NN + n0 + r1] = ds1;
        }
        float* p0 = pnum + ((size_t)seg*NN + n0 + r0)*64;
        float* p1 = pnum + ((size_t)seg*NN + n0 + r1)*64;
        #pragma unroll
        for (int dt = 0; dt < 8; dt++) {
            *(float2*)(p0 + dt*8 + c2) = make_float2(acc[dt][0], acc[dt][1]);
            *(float2*)(p1 + dt*8 + c2) = make_float2(acc[dt][2], acc[dt][3]);
        }
    } else {
        float inv0 = 1.0f / ds0, inv1 = 1.0f / ds1;
        #pragma unroll
        for (int dt = 0; dt < 8; dt++) {
            float z0 = acc[dt][0]*inv0, z1 = acc[dt][1]*inv0;
            float z2 = acc[dt][2]*inv1, z3 = acc[dt][3]*inv1;
            z0 = (z0 > 0.f) ? z0 : expm1f(z0);
            z1 = (z1 > 0.f) ? z1 : expm1f(z1);
            z2 = (z2 > 0.f) ? z2 : expm1f(z2);
            z3 = (z3 > 0.f) ? z3 : expm1f(z3);
            uint32_t h0, l0, h1, l1;
            packsplit(z0, z1, h0, l0);
            packsplit(z2, z3, h1, l1);
            size_t o0 = (size_t)(n0+r0)*ldout + coloff + dt*8 + c2;
            size_t o1 = (size_t)(n0+r1)*ldout + coloff + dt*8 + c2;
            *(uint32_t*)(out_hi + o0) = h0;
            *(uint32_t*)(out_lo + o0) = l0;
            *(uint32_t*)(out_hi + o1) = h1;
            *(uint32_t*)(out_lo + o1) = l1;
        }
    }
}

// ------------- combine K-split partials -------------
__global__ void k_comb(const float* __restrict__ pnum, const float* __restrict__ pden,
                       float* __restrict__ h2)
{
    int gw = (blockIdx.x*blockDim.x + threadIdx.x) >> 5;
    int lane = threadIdx.x & 31;
    if (gw >= NN) return;
    float den = 0.f;
    #pragma unroll
    for (int s = 0; s < SPLIT; s++) den += pden[(size_t)s*NN + gw];
    float a0 = 0.f, a1 = 0.f;
    #pragma unroll
    for (int s = 0; s < SPLIT; s++) {
        const float* p = pnum + ((size_t)s*NN + gw)*64;
        a0 += p[lane]; a1 += p[lane+32];
    }
    float inv = 1.0f / den;
    h2[(size_t)gw*64 + lane]      = a0*inv;
    h2[(size_t)gw*64 + lane + 32] = a1*inv;
}

// ------------- ELU + row log_softmax -------------
__global__ void k_final(const float* __restrict__ h2, float* __restrict__ out) {
    int gw = (blockIdx.x*blockDim.x + threadIdx.x) >> 5;
    int lane = threadIdx.x & 31;
    if (gw >= NN) return;
    const float* row = h2 + (size_t)gw*64;
    float z0 = row[lane], z1 = row[lane+32];
    z0 = (z0 > 0.f) ? z0 : expm1f(z0);
    z1 = (z1 > 0.f) ? z1 : expm1f(z1);
    float mx = fmaxf(z0, z1);
    #pragma unroll
    for (int o = 16; o; o >>= 1) mx = fmaxf(mx, __shfl_xor_sync(0xFFFFFFFFu, mx, o));
    float se = expf(z0 - mx) + expf(z1 - mx);
    #pragma unroll
    for (int o = 16; o; o >>= 1) se += __shfl_xor_sync(0xFFFFFFFFu, se, o);
    float lse = mx + logf(se);
    out[(size_t)gw*64 + lane]      = z0 - lse;
    out[(size_t)gw*64 + lane + 32] = z1 - lse;
}

extern "C" void kernel_launch(void* const* d_in, const int* in_sizes, int n_in,
                              void* d_out, int out_size)
{
    const float* x     = (const float*)d_in[0];
    const int*   adj   = (const int*)  d_in[1];
    const float* W     = (const float*)d_in[2];
    const float* asrc  = (const float*)d_in[3];
    const float* adst  = (const float*)d_in[4];
    const float* Wo    = (const float*)d_in[5];
    const float* aosrc = (const float*)d_in[6];
    const float* aodst = (const float*)d_in[7];
    float* out = (float*)d_out;

    void* sp = nullptr;  cudaGetSymbolAddress(&sp, g_scratch);
    void* bpv = nullptr; cudaGetSymbolAddress(&bpv, g_bits);
    void* bfv = nullptr; cudaGetSymbolAddress(&bfv, g_bf);
    float* S = (float*)sp;
    unsigned* bits = (unsigned*)bpv;
    __nv_bfloat16* BF = (__nv_bfloat16*)bfv;

    float* Wh    = S;
    float* Who   = Wh  + (size_t)NN*FF;
    float* h2    = Who + (size_t)NN*DD;
    float* fsrcM = h2  + (size_t)NN*DD;
    float* ApM   = fsrcM + (size_t)HH*NN;
    float* AnM   = ApM   + (size_t)HH*NN;
    float4* pkM  = (float4*)(AnM + (size_t)HH*NN);
    float* fsrcO = (float*)(pkM + (size_t)HH*NN);
    float* ApO   = fsrcO + NN;
    float* AnO   = ApO + NN;
    float4* pkO  = (float4*)(AnO + NN);
    float* pnum  = (float*)(pkO + NN);
    float* pden  = pnum + (size_t)SPLIT*NN*DD;

    __nv_bfloat16* x_hi   = BF;
    __nv_bfloat16* x_lo   = x_hi   + (size_t)NN*FF;
    __nv_bfloat16* Wt_hi  = x_lo   + (size_t)NN*FF;
    __nv_bfloat16* Wt_lo  = Wt_hi  + (size_t)HH*FF*DD;
    __nv_bfloat16* WhT_hi = Wt_lo  + (size_t)HH*FF*DD;
    __nv_bfloat16* WhT_lo = WhT_hi + (size_t)NN*FF;
    __nv_bfloat16* hc_hi  = WhT_lo + (size_t)NN*FF;
    __nv_bfloat16* hc_lo  = hc_hi  + (size_t)NN*FF;
    __nv_bfloat16* Wot_hi = hc_lo  + (size_t)NN*FF;
    __nv_bfloat16* Wot_lo = Wot_hi + (size_t)FF*DD;
    __nv_bfloat16* WoT_hi = Wot_lo + (size_t)FF*DD;
    __nv_bfloat16* WoT_lo = WoT_hi + (size_t)NN*DD;

    cudaFuncSetAttribute(k_gemm_tc, cudaFuncAttributeMaxDynamicSharedMemorySize, SMEM_G);
    cudaFuncSetAttribute(k_attn_mma, cudaFuncAttributeMaxDynamicSharedMemorySize, SMEM_ATT);

    // 1) adj -> bitmask
    {
        long long threads = (long long)NN*(NN/32)*32;
        k_bits<<<(unsigned)((threads + 255)/256), 256>>>(adj, bits);
    }
    // 2) split x; transpose+split W (per head)
    k_split<<<(NN*FF/4 + 255)/256, 256>>>(x, x_hi, x_lo, NN*FF/4);
    k_tsplitg<<<dim3(FF/32, DD/32, HH), 256>>>(W, FF, DD, Wt_hi, Wt_lo);
    // 3) Wh = x @ W (HMMA, pipelined)
    k_gemm_tc<<<dim3(NN/128, FF/64), 256, SMEM_G>>>(x_hi, x_lo, Wt_hi, Wt_lo, Wh, FF, FF);
    // 4) attention scalars (main)
    k_fexp<<<(HH*NN*32 + 255)/256, 256>>>(Wh, FF, asrc, adst, fsrcM, ApM, AnM, pkM, HH);
    // 5) transpose+split Wh -> WhT
    k_tsplitg<<<dim3(NN/32, FF/32, 1), 256>>>(Wh, NN, FF, WhT_hi, WhT_lo);
    // 6) main attention -> hcat hi/lo (ELU applied)
    k_attn_mma<<<dim3(NN/128, HH, 1), 256, SMEM_ATT>>>(WhT_hi, WhT_lo,
        fsrcM, ApM, AnM, pkM, bits, hc_hi, hc_lo, FF, NN, nullptr, nullptr, 0);
    // 7) transpose+split Wo; Who = hcat @ Wo (HMMA)
    k_tsplitg<<<dim3(FF/32, DD/32, 1), 256>>>(Wo, FF, DD, Wot_hi, Wot_lo);
    k_gemm_tc<<<dim3(NN/128, DD/64), 256, SMEM_G>>>(hc_hi, hc_lo, Wot_hi, Wot_lo, Who, DD, FF);
    // 8) out-head scalars
    k_fexp<<<(NN*32 + 255)/256, 256>>>(Who, DD, aosrc, aodst, fsrcO, ApO, AnO, pkO, 1);
    // 9) transpose+split Who
    k_tsplitg<<<dim3(NN/32, DD/32, 1), 256>>>(Who, NN, DD, WoT_hi, WoT_lo);
    // 10) out-head attention, 8-way K-split
    k_attn_mma<<<dim3(NN/128, 1, SPLIT), 256, SMEM_ATT>>>(WoT_hi, WoT_lo,
        fsrcO, ApO, AnO, pkO, bits, nullptr, nullptr, DD, NN/SPLIT, pnum, pden, 1);
    // 11) combine + final
    k_comb<<<(NN*32 + 255)/256, 256>>>(pnum, pden, h2);
    k_final<<<(NN*32 + 255)/256, 256>>>(h2, out);
}

// round 6
// speedup vs baseline: 3.2125x; 1.1154x over previous
#include <cuda_runtime.h>
#include <cuda_bf16.h>
#include <cstdint>

#define NN 4096
#define FF 512
#define DD 64
#define HH 8
#define SPLIT 8

// ---------------------------------------------------------------- helpers
__device__ __forceinline__ void mma_bf16(float* d, const uint32_t* a, const uint32_t* b) {
    asm volatile("mma.sync.aligned.m16n8k16.row.col.f32.bf16.bf16.f32 "
        "{%0,%1,%2,%3}, {%4,%5,%6,%7}, {%8,%9}, {%0,%1,%2,%3};"
        : "+f"(d[0]), "+f"(d[1]), "+f"(d[2]), "+f"(d[3])
        : "r"(a[0]), "r"(a[1]), "r"(a[2]), "r"(a[3]), "r"(b[0]), "r"(b[1]));
}
__device__ __forceinline__ void ldsm_x4(uint32_t* r, uint32_t addr) {
    asm volatile("ldmatrix.sync.aligned.m8n8.x4.shared.b16 {%0,%1,%2,%3}, [%4];"
        : "=r"(r[0]), "=r"(r[1]), "=r"(r[2]), "=r"(r[3]) : "r"(addr));
}
__device__ __forceinline__ uint32_t smem_to_u32(const void* p) {
    uint32_t a;
    asm("{ .reg .u64 t; cvta.to.shared.u64 t, %1; cvt.u32.u64 %0, t; }" : "=r"(a) : "l"(p));
    return a;
}
__device__ __forceinline__ void cp16(uint32_t s, const void* g) {
    asm volatile("cp.async.cg.shared.global [%0], [%1], 16;" :: "r"(s), "l"(g));
}
#define CP_COMMIT() asm volatile("cp.async.commit_group;" ::: "memory")
#define CP_WAIT(N)  asm volatile("cp.async.wait_group %0;" :: "n"(N) : "memory")

__device__ __forceinline__ void packsplit(float a, float b, uint32_t& hi, uint32_t& lo) {
    __nv_bfloat162 h = __floats2bfloat162_rn(a, b);
    hi = *(uint32_t*)&h;
    float ra = a - __bfloat162float(h.x);
    float rb = b - __bfloat162float(h.y);
    __nv_bfloat162 l = __floats2bfloat162_rn(ra, rb);
    lo = *(uint32_t*)&l;
}
__device__ __forceinline__ float wv2(float4 s, float nfs, float APr, float ANr, unsigned bit) {
    bool p = s.x >= nfs;
    float w = (p ? APr : ANr) * (p ? s.y : s.z);
    return bit ? w : 0.f;
}
// round pair to bf16x2, return bits, add rounded values into dsum (consistency!)
__device__ __forceinline__ uint32_t roundacc(float a, float b, float& dsum) {
    __nv_bfloat162 h = __floats2bfloat162_rn(a, b);
    dsum += __bfloat162float(h.x) + __bfloat162float(h.y);
    return *(uint32_t*)&h;
}

// ---------------------------------------------------------------- scratch
#define SCR_FLOATS (NN*DD + 3*HH*NN + 4*HH*NN + 3*NN + 4*NN + SPLIT*NN*DD + SPLIT*NN)
__device__ __align__(16) float g_scratch[SCR_FLOATS];
__device__ unsigned g_bits[NN*(NN/32)];
#define BF_ELEMS (2*NN*FF + 2*HH*FF*DD + 2*NN*FF + 2*NN*FF + 2*FF*DD + 2*NN*DD)
__device__ __align__(16) __nv_bfloat16 g_bf[BF_ELEMS];

// ---------------- prep: split x (z=0) + transpose/split W, Wo (z=1) ----------------
__global__ __launch_bounds__(256) void k_prep(
    const float* __restrict__ x, const float* __restrict__ W, const float* __restrict__ Wo,
    __nv_bfloat16* __restrict__ x_hi, __nv_bfloat16* __restrict__ x_lo,
    __nv_bfloat16* __restrict__ Wt_hi, __nv_bfloat16* __restrict__ Wt_lo,
    __nv_bfloat16* __restrict__ Wot_hi, __nv_bfloat16* __restrict__ Wot_lo)
{
    __shared__ float tile[32][33];
    int t = threadIdx.x;
    if (blockIdx.z == 0) {
        int i = blockIdx.x*256 + t;
        if (i >= NN*FF/4) return;
        float4 v = *(const float4*)(x + (size_t)i*4);
        uint32_t h0, l0, h1, l1;
        packsplit(v.x, v.y, h0, l0);
        packsplit(v.z, v.w, h1, l1);
        *(uint32_t*)(x_hi + (size_t)i*4)     = h0;
        *(uint32_t*)(x_hi + (size_t)i*4 + 2) = h1;
        *(uint32_t*)(x_lo + (size_t)i*4)     = l0;
        *(uint32_t*)(x_lo + (size_t)i*4 + 2) = l1;
        return;
    }
    // transpose+split tiles: A[R=FF][C=DD] -> T[C][R]
    const float* A; __nv_bfloat16 *Thi, *Tlo;
    int bxx, byy;
    int bx = blockIdx.x;
    if (bx < 256) {                 // W per head
        int h = bx >> 5, rem = bx & 31;
        bxx = rem & 15; byy = rem >> 4;
        A = W + (size_t)h*FF*DD;
        Thi = Wt_hi + (size_t)h*FF*DD;
        Tlo = Wt_lo + (size_t)h*FF*DD;
    } else if (bx < 288) {          // Wo
        int idx = bx - 256;
        bxx = idx & 15; byy = idx >> 4;
        A = Wo; Thi = Wot_hi; Tlo = Wot_lo;
    } else return;
    int n0 = bxx*32, c0 = byy*32;
    int tx = t & 31, ty = t >> 5;
    #pragma unroll
    for (int i = 0; i < 4; i++) {
        int nr = ty*4 + i;
        tile[nr][tx] = A[(size_t)(n0+nr)*DD + c0 + tx];
    }
    __syncthreads();
    #pragma unroll
    for (int i = 0; i < 4; i++) {
        int cr = ty*4 + i;
        float v = tile[tx][cr];
        __nv_bfloat16 h = __float2bfloat16(v);
        Thi[(size_t)(c0+cr)*FF + n0 + tx] = h;
        Tlo[(size_t)(c0+cr)*FF + n0 + tx] = __float2bfloat16(v - __bfloat162float(h));
    }
}

// ---------------- adj -> bitmask ----------------
__global__ void k_bits(const int* __restrict__ adj, unsigned* __restrict__ bits) {
    int gw = (blockIdx.x * blockDim.x + threadIdx.x) >> 5;
    int lane = threadIdx.x & 31;
    if (gw >= NN*(NN/32)) return;
    int v = adj[(size_t)gw*32 + lane];
    unsigned b = __ballot_sync(0xFFFFFFFFu, v > 0);
    if (lane == 0) bits[gw] = b;
}

// ---------------- fused HMMA GEMM: C-block [128 x 64] per CTA ----------------
// epilogue: fexp scalars + transposed hi/lo split written directly
#define G_AH 0
#define G_AL 18432
#define G_BH 36864
#define G_BL 46080
#define G_STAGE 55296
#define SMEM_G (2*G_STAGE)

__global__ __launch_bounds__(256, 2) void k_gemm_f(
    const __nv_bfloat16* __restrict__ Ah, const __nv_bfloat16* __restrict__ Al,
    const __nv_bfloat16* __restrict__ Bh, const __nv_bfloat16* __restrict__ Bl, int K,
    const float* __restrict__ av_src, const float* __restrict__ av_dst,
    float* __restrict__ fsrc, float* __restrict__ Ap, float* __restrict__ An,
    float4* __restrict__ pk,
    __nv_bfloat16* __restrict__ outT_hi, __nv_bfloat16* __restrict__ outT_lo)
{
    extern __shared__ char smem[];
    uint32_t sb = smem_to_u32(smem);
    int t = threadIdx.x;
    int wid = t >> 5, lane = t & 31;
    int n0 = blockIdx.x*128, c0 = blockIdx.y*64;
    int fbase = blockIdx.y*NN;
    float acc[8][4];
    #pragma unroll
    for (int i = 0; i < 8; i++)
        #pragma unroll
        for (int j = 0; j < 4; j++) acc[i][j] = 0.f;

    int mrow = wid*16 + (lane&7) + ((lane>>3)&1)*8;
    uint32_t aOff = (uint32_t)(mrow*72 + (lane>>4)*8)*2;
    uint32_t bOff = (uint32_t)((lane&7)*72 + (lane>>3)*8)*2;

    int chunks = K/64;
    auto stage = [&](int kc) {
        uint32_t dst = sb + (uint32_t)(kc & 1)*G_STAGE;
        int k0 = kc*64;
        #pragma unroll
        for (int i = 0; i < 4; i++) {
            int idx = t + i*256;
            int row = idx >> 3, k16 = idx & 7;
            cp16(dst + G_AH + row*144 + k16*16, Ah + (size_t)(n0+row)*K + k0 + k16*8);
            cp16(dst + G_AL + row*144 + k16*16, Al + (size_t)(n0+row)*K + k0 + k16*8);
        }
        #pragma unroll
        for (int i = 0; i < 2; i++) {
            int idx = t + i*256;
            int col = idx >> 3, k16 = idx & 7;
            cp16(dst + G_BH + col*144 + k16*16, Bh + (size_t)(c0+col)*K + k0 + k16*8);
            cp16(dst + G_BL + col*144 + k16*16, Bl + (size_t)(c0+col)*K + k0 + k16*8);
        }
        CP_COMMIT();
    };

    stage(0);
    for (int kc = 0; kc < chunks; kc++) {
        if (kc + 1 < chunks) { stage(kc + 1); CP_WAIT(1); }
        else                 { CP_WAIT(0); }
        __syncthreads();
        uint32_t sbuf = sb + (uint32_t)(kc & 1)*G_STAGE;
        #pragma unroll
        for (int ko = 0; ko < 2; ko++) {
            uint32_t ah[8], al[8];
            ldsm_x4(ah+0, sbuf + G_AH + aOff + ko*64);
            ldsm_x4(ah+4, sbuf + G_AH + aOff + ko*64 + 32);
            ldsm_x4(al+0, sbuf + G_AL + aOff + ko*64);
            ldsm_x4(al+4, sbuf + G_AL + aOff + ko*64 + 32);
            #pragma unroll
            for (int dt = 0; dt < 8; dt++) {
                uint32_t bh[4], bl[4];
                ldsm_x4(bh, sbuf + G_BH + bOff + dt*1152 + ko*64);
                ldsm_x4(bl, sbuf + G_BL + bOff + dt*1152 + ko*64);
                mma_bf16(acc[dt], ah+0, bh+0);
                mma_bf16(acc[dt], ah+4, bh+2);
                mma_bf16(acc[dt], ah+0, bl+0);
                mma_bf16(acc[dt], ah+4, bl+2);
                mma_bf16(acc[dt], al+0, bh+0);
                mma_bf16(acc[dt], al+4, bh+2);
            }
        }
        __syncthreads();
    }

    int qr = lane >> 2, c2 = (lane & 3)*2;
    int r0 = wid*16 + qr, r1 = r0 + 8;

    // ---- fexp epilogue: row dot-products with a_src/a_dst, quad reduce ----
    float fs0 = 0.f, fs1 = 0.f, fd0 = 0.f, fd1 = 0.f;
    #pragma unroll
    for (int dt = 0; dt < 8; dt++) {
        float a0 = av_src[c0 + dt*8 + c2], a1 = av_src[c0 + dt*8 + c2 + 1];
        float b0 = av_dst[c0 + dt*8 + c2], b1 = av_dst[c0 + dt*8 + c2 + 1];
        fs0 += acc[dt][0]*a0 + acc[dt][1]*a1;
        fs1 += acc[dt][2]*a0 + acc[dt][3]*a1;
        fd0 += acc[dt][0]*b0 + acc[dt][1]*b1;
        fd1 += acc[dt][2]*b0 + acc[dt][3]*b1;
    }
    #pragma unroll
    for (int o = 1; o <= 2; o <<= 1) {
        fs0 += __shfl_xor_sync(0xFFFFFFFFu, fs0, o);
        fs1 += __shfl_xor_sync(0xFFFFFFFFu, fs1, o);
        fd0 += __shfl_xor_sync(0xFFFFFFFFu, fd0, o);
        fd1 += __shfl_xor_sync(0xFFFFFFFFu, fd1, o);
    }
    if ((lane & 3) == 0) {
        int na = fbase + n0 + r0, nb = fbase + n0 + r1;
        fsrc[na] = fs0; Ap[na] = expf(fs0); An[na] = expf(0.2f*fs0);
        pk[na] = make_float4(fd0, expf(fd0), expf(0.2f*fd0), 0.f);
        fsrc[nb] = fs1; Ap[nb] = expf(fs1); An[nb] = expf(0.2f*fs1);
        pk[nb] = make_float4(fd1, expf(fd1), expf(0.2f*fd1), 0.f);
    }

    // ---- transposed hi/lo write via smem (stride 132 floats, conflict-free) ----
    float* sT = (float*)smem;
    #pragma unroll
    for (int dt = 0; dt < 8; dt++) {
        int c = dt*8 + c2;
        sT[(c  )*132 + r0] = acc[dt][0];
        sT[(c+1)*132 + r0] = acc[dt][1];
        sT[(c  )*132 + r1] = acc[dt][2];
        sT[(c+1)*132 + r1] = acc[dt][3];
    }
    __syncthreads();
    {
        int c = t >> 2;
        int nb = (t & 3)*32;
        const float* src = sT + c*132 + nb;
        __nv_bfloat16* dh = outT_hi + (size_t)(c0 + c)*NN + n0 + nb;
        __nv_bfloat16* dl = outT_lo + (size_t)(c0 + c)*NN + n0 + nb;
        #pragma unroll
        for (int j = 0; j < 16; j++) {
            uint32_t hi, lo;
            packsplit(src[j*2], src[j*2+1], hi, lo);
            *(uint32_t*)(dh + j*2) = hi;
            *(uint32_t*)(dl + j*2) = lo;
        }
    }
}

// ------------- attn: w single-bf16 in A-frags + consistent denom, V hi/lo, 3-stage cp.async -------------
#define VH_OFF 0
#define VL_OFF 9216
#define PK_OFF 18432
#define STAGE_B 19456
#define SMEM_ATT (3*STAGE_B)

__global__ __launch_bounds__(256, 2) void k_attn_mma(
    const __nv_bfloat16* __restrict__ VT_hi,
    const __nv_bfloat16* __restrict__ VT_lo,
    const float* __restrict__ fsrc, const float* __restrict__ Ap, const float* __restrict__ An,
    const float4* __restrict__ pk,
    const unsigned* __restrict__ bits,
    __nv_bfloat16* __restrict__ out_hi, __nv_bfloat16* __restrict__ out_lo, int ldout,
    int mPerCta, float* __restrict__ pnum, float* __restrict__ pden, int partial)
{
    extern __shared__ char smem[];
    uint32_t sb = smem_to_u32(smem);
    int t = threadIdx.x;
    int wid = t >> 5, lane = t & 31;
    int head = blockIdx.y;
    int seg = blockIdx.z;
    int n0 = blockIdx.x * 128;
    int fbase = head * NN;
    int coloff = head * 64;
    int mStart = seg * mPerCta;
    int iters = mPerCta / 64;

    int qr = lane >> 2;
    int c2 = (lane & 3) * 2;
    int r0 = wid*16 + qr;
    int r1 = r0 + 8;

    float nfs0 = -fsrc[fbase + n0 + r0];
    float nfs1 = -fsrc[fbase + n0 + r1];
    float Ap0 = Ap[fbase + n0 + r0], Ap1 = Ap[fbase + n0 + r1];
    float An0 = An[fbase + n0 + r0], An1 = An[fbase + n0 + r1];
    const unsigned* brow0 = bits + (size_t)(n0 + r0)*(NN/32);
    const unsigned* brow1 = bits + (size_t)(n0 + r1)*(NN/32);

    float acc[8][4];
    #pragma unroll
    for (int i = 0; i < 8; i++)
        #pragma unroll
        for (int j = 0; j < 4; j++) acc[i][j] = 0.f;
    float ds0 = 0.f, ds1 = 0.f;

    auto stage = [&](int it) {
        uint32_t dst = sb + (uint32_t)(it % 3)*STAGE_B;
        int m0 = mStart + it*64;
        #pragma unroll
        for (int i = 0; i < 2; i++) {
            int idx = t + i*256;
            int d = idx >> 3, k16 = idx & 7;
            cp16(dst + VH_OFF + d*144 + k16*16, VT_hi + (size_t)(coloff + d)*NN + m0 + k16*8);
            cp16(dst + VL_OFF + d*144 + k16*16, VT_lo + (size_t)(coloff + d)*NN + m0 + k16*8);
        }
        if (t < 64) cp16(dst + PK_OFF + t*16, pk + fbase + m0 + t);
        CP_COMMIT();
    };

    stage(0);
    if (iters > 1) stage(1);
    uint32_t bOff = (uint32_t)((lane & 7)*72 + (lane >> 3)*8)*2;

    for (int it = 0; it < iters; it++) {
        if (it + 2 < iters)      { stage(it + 2); CP_WAIT(2); }
        else if (it + 1 < iters) { CP_WAIT(1); }
        else                     { CP_WAIT(0); }
        __syncthreads();

        int buf = it % 3;
        uint32_t sbuf = sb + (uint32_t)buf*STAGE_B;
        const float4* pks = (const float4*)(smem + buf*STAGE_B + PK_OFF);
        int m0 = mStart + it*64;
        int wbase = m0 >> 5;
        unsigned b00 = brow0[wbase], b01 = brow0[wbase+1];
        unsigned b10 = brow1[wbase], b11 = brow1[wbase+1];

        uint32_t ah[4][4];
        #pragma unroll
        for (int kc = 0; kc < 4; kc++) {
            int mA = kc*16 + c2;
            int mB = mA + 8;
            float4 sA0 = pks[mA], sA1 = pks[mA+1];
            float4 sB0 = pks[mB], sB1 = pks[mB+1];
            unsigned w0 = (kc < 2) ? b00 : b01;
            unsigned w1 = (kc < 2) ? b10 : b11;
            int jA = mA & 31, jB = mB & 31;
            float wA0r0 = wv2(sA0, nfs0, Ap0, An0, (w0 >> jA) & 1u);
            float wA1r0 = wv2(sA1, nfs0, Ap0, An0, (w0 >> (jA+1)) & 1u);
            float wA0r1 = wv2(sA0, nfs1, Ap1, An1, (w1 >> jA) & 1u);
            float wA1r1 = wv2(sA1, nfs1, Ap1, An1, (w1 >> (jA+1)) & 1u);
            float wB0r0 = wv2(sB0, nfs0, Ap0, An0, (w0 >> jB) & 1u);
            float wB1r0 = wv2(sB1, nfs0, Ap0, An0, (w0 >> (jB+1)) & 1u);
            float wB0r1 = wv2(sB0, nfs1, Ap1, An1, (w1 >> jB) & 1u);
            float wB1r1 = wv2(sB1, nfs1, Ap1, An1, (w1 >> (jB+1)) & 1u);
            ah[kc][0] = roundacc(wA0r0, wA1r0, ds0);
            ah[kc][1] = roundacc(wA0r1, wA1r1, ds1);
            ah[kc][2] = roundacc(wB0r0, wB1r0, ds0);
            ah[kc][3] = roundacc(wB0r1, wB1r1, ds1);
        }

        #pragma unroll
        for (int ko = 0; ko < 2; ko++) {
            #pragma unroll
            for (int dt = 0; dt < 8; dt++) {
                uint32_t bh[4], bl[4];
                ldsm_x4(bh, sbuf + VH_OFF + bOff + dt*1152 + ko*64);
                ldsm_x4(bl, sbuf + VL_OFF + bOff + dt*1152 + ko*64);
                mma_bf16(acc[dt], ah[2*ko],   bh+0);
                mma_bf16(acc[dt], ah[2*ko+1], bh+2);
                mma_bf16(acc[dt], ah[2*ko],   bl+0);
                mma_bf16(acc[dt], ah[2*ko+1], bl+2);
            }
        }
        __syncthreads();
    }

    ds0 += __shfl_xor_sync(0xFFFFFFFFu, ds0, 1);
    ds0 += __shfl_xor_sync(0xFFFFFFFFu, ds0, 2);
    ds1 += __shfl_xor_sync(0xFFFFFFFFu, ds1, 1);
    ds1 += __shfl_xor_sync(0xFFFFFFFFu, ds1, 2);

    if (partial) {
        if ((lane & 3) == 0) {
            pden[(size_t)seg*NN + n0 + r0] = ds0;
            pden[(size_t)seg*NN + n0 + r1] = ds1;
        }
        float* p0 = pnum + ((size_t)seg*NN + n0 + r0)*64;
        float* p1 = pnum + ((size_t)seg*NN + n0 + r1)*64;
        #pragma unroll
        for (int dt = 0; dt < 8; dt++) {
            *(float2*)(p0 + dt*8 + c2) = make_float2(acc[dt][0], acc[dt][1]);
            *(float2*)(p1 + dt*8 + c2) = make_float2(acc[dt][2], acc[dt][3]);
        }
    } else {
        float inv0 = 1.0f / ds0, inv1 = 1.0f / ds1;
        #pragma unroll
        for (int dt = 0; dt < 8; dt++) {
            float z0 = acc[dt][0]*inv0, z1 = acc[dt][1]*inv0;
            float z2 = acc[dt][2]*inv1, z3 = acc[dt][3]*inv1;
            z0 = (z0 > 0.f) ? z0 : expm1f(z0);
            z1 = (z1 > 0.f) ? z1 : expm1f(z1);
            z2 = (z2 > 0.f) ? z2 : expm1f(z2);
            z3 = (z3 > 0.f) ? z3 : expm1f(z3);
            uint32_t h0, l0, h1, l1;
            packsplit(z0, z1, h0, l0);
            packsplit(z2, z3, h1, l1);
            size_t o0 = (size_t)(n0+r0)*ldout + coloff + dt*8 + c2;
            size_t o1 = (size_t)(n0+r1)*ldout + coloff + dt*8 + c2;
            *(uint32_t*)(out_hi + o0) = h0;
            *(uint32_t*)(out_lo + o0) = l0;
            *(uint32_t*)(out_hi + o1) = h1;
            *(uint32_t*)(out_lo + o1) = l1;
        }
    }
}

// ------------- combine K-split partials -------------
__global__ void k_comb(const float* __restrict__ pnum, const float* __restrict__ pden,
                       float* __restrict__ h2)
{
    int gw = (blockIdx.x*blockDim.x + threadIdx.x) >> 5;
    int lane = threadIdx.x & 31;
    if (gw >= NN) return;
    float den = 0.f;
    #pragma unroll
    for (int s = 0; s < SPLIT; s++) den += pden[(size_t)s*NN + gw];
    float a0 = 0.f, a1 = 0.f;
    #pragma unroll
    for (int s = 0; s < SPLIT; s++) {
        const float* p = pnum + ((size_t)s*NN + gw)*64;
        a0 += p[lane]; a1 += p[lane+32];
    }
    float inv = 1.0f / den;
    h2[(size_t)gw*64 + lane]      = a0*inv;
    h2[(size_t)gw*64 + lane + 32] = a1*inv;
}

// ------------- ELU + row log_softmax -------------
__global__ void k_final(const float* __restrict__ h2, float* __restrict__ out) {
    int gw = (blockIdx.x*blockDim.x + threadIdx.x) >> 5;
    int lane = threadIdx.x & 31;
    if (gw >= NN) return;
    const float* row = h2 + (size_t)gw*64;
    float z0 = row[lane], z1 = row[lane+32];
    z0 = (z0 > 0.f) ? z0 : expm1f(z0);
    z1 = (z1 > 0.f) ? z1 : expm1f(z1);
    float mx = fmaxf(z0, z1);
    #pragma unroll
    for (int o = 16; o; o >>= 1) mx = fmaxf(mx, __shfl_xor_sync(0xFFFFFFFFu, mx, o));
    float se = expf(z0 - mx) + expf(z1 - mx);
    #pragma unroll
    for (int o = 16; o; o >>= 1) se += __shfl_xor_sync(0xFFFFFFFFu, se, o);
    float lse = mx + logf(se);
    out[(size_t)gw*64 + lane]      = z0 - lse;
    out[(size_t)gw*64 + lane + 32] = z1 - lse;
}

extern "C" void kernel_launch(void* const* d_in, const int* in_sizes, int n_in,
                              void* d_out, int out_size)
{
    const float* x     = (const float*)d_in[0];
    const int*   adj   = (const int*)  d_in[1];
    const float* W     = (const float*)d_in[2];
    const float* asrc  = (const float*)d_in[3];
    const float* adst  = (const float*)d_in[4];
    const float* Wo    = (const float*)d_in[5];
    const float* aosrc = (const float*)d_in[6];
    const float* aodst = (const float*)d_in[7];
    float* out = (float*)d_out;

    void* sp = nullptr;  cudaGetSymbolAddress(&sp, g_scratch);
    void* bpv = nullptr; cudaGetSymbolAddress(&bpv, g_bits);
    void* bfv = nullptr; cudaGetSymbolAddress(&bfv, g_bf);
    float* S = (float*)sp;
    unsigned* bits = (unsigned*)bpv;
    __nv_bfloat16* BF = (__nv_bfloat16*)bfv;

    float* h2    = S;
    float* fsrcM = h2  + (size_t)NN*DD;
    float* ApM   = fsrcM + (size_t)HH*NN;
    float* AnM   = ApM   + (size_t)HH*NN;
    float4* pkM  = (float4*)(AnM + (size_t)HH*NN);
    float* fsrcO = (float*)(pkM + (size_t)HH*NN);
    float* ApO   = fsrcO + NN;
    float* AnO   = ApO + NN;
    float4* pkO  = (float4*)(AnO + NN);
    float* pnum  = (float*)(pkO + NN);
    float* pden  = pnum + (size_t)SPLIT*NN*DD;

    __nv_bfloat16* x_hi   = BF;
    __nv_bfloat16* x_lo   = x_hi   + (size_t)NN*FF;
    __nv_bfloat16* Wt_hi  = x_lo   + (size_t)NN*FF;
    __nv_bfloat16* Wt_lo  = Wt_hi  + (size_t)HH*FF*DD;
    __nv_bfloat16* WhT_hi = Wt_lo  + (size_t)HH*FF*DD;
    __nv_bfloat16* WhT_lo = WhT_hi + (size_t)NN*FF;
    __nv_bfloat16* hc_hi  = WhT_lo + (size_t)NN*FF;
    __nv_bfloat16* hc_lo  = hc_hi  + (size_t)NN*FF;
    __nv_bfloat16* Wot_hi = hc_lo  + (size_t)NN*FF;
    __nv_bfloat16* Wot_lo = Wot_hi + (size_t)FF*DD;
    __nv_bfloat16* WoT_hi = Wot_lo + (size_t)FF*DD;
    __nv_bfloat16* WoT_lo = WoT_hi + (size_t)NN*DD;

    cudaFuncSetAttribute(k_gemm_f, cudaFuncAttributeMaxDynamicSharedMemorySize, SMEM_G);
    cudaFuncSetAttribute(k_attn_mma, cudaFuncAttributeMaxDynamicSharedMemorySize, SMEM_ATT);

    // 0) prep: split x, transpose+split W and Wo
    k_prep<<<dim3(2048, 1, 2), 256>>>(x, W, Wo, x_hi, x_lo, Wt_hi, Wt_lo, Wot_hi, Wot_lo);
    // 1) adj -> bitmask
    {
        long long threads = (long long)NN*(NN/32)*32;
        k_bits<<<(unsigned)((threads + 255)/256), 256>>>(adj, bits);
    }
    // 2) gemm1 fused: Wh = x @ W -> WhT hi/lo + main fexp scalars
    k_gemm_f<<<dim3(NN/128, FF/64), 256, SMEM_G>>>(x_hi, x_lo, Wt_hi, Wt_lo, FF,
        asrc, adst, fsrcM, ApM, AnM, pkM, WhT_hi, WhT_lo);
    // 3) main attention -> hcat hi/lo (ELU applied)    [profiled launch]
    k_attn_mma<<<dim3(NN/128, HH, 1), 256, SMEM_ATT>>>(WhT_hi, WhT_lo,
        fsrcM, ApM, AnM, pkM, bits, hc_hi, hc_lo, FF, NN, nullptr, nullptr, 0);
    // 4) gemm2 fused: Who = hcat @ Wo -> WhoT hi/lo + out-head fexp scalars
    k_gemm_f<<<dim3(NN/128, 1), 256, SMEM_G>>>(hc_hi, hc_lo, Wot_hi, Wot_lo, FF,
        aosrc, aodst, fsrcO, ApO, AnO, pkO, WoT_hi, WoT_lo);
    // 5) out-head attention, 8-way K-split
    k_attn_mma<<<dim3(NN/128, 1, SPLIT), 256, SMEM_ATT>>>(WoT_hi, WoT_lo,
        fsrcO, ApO, AnO, pkO, bits, nullptr, nullptr, DD, NN/SPLIT, pnum, pden, 1);
    // 6) combine + 7) final
    k_comb<<<(NN*32 + 255)/256, 256>>>(pnum, pden, h2);
    k_final<<<(NN*32 + 255)/256, 256>>>(h2, out);
}

// round 7
// speedup vs baseline: 3.4423x; 1.0715x over previous
#include <cuda_runtime.h>
#include <cuda_bf16.h>
#include <cstdint>

#define NN 4096
#define FF 512
#define DD 64
#define HH 8
#define SPLIT 8

// ---------------------------------------------------------------- helpers
__device__ __forceinline__ void mma_bf16(float* d, const uint32_t* a, const uint32_t* b) {
    asm volatile("mma.sync.aligned.m16n8k16.row.col.f32.bf16.bf16.f32 "
        "{%0,%1,%2,%3}, {%4,%5,%6,%7}, {%8,%9}, {%0,%1,%2,%3};"
        : "+f"(d[0]), "+f"(d[1]), "+f"(d[2]), "+f"(d[3])
        : "r"(a[0]), "r"(a[1]), "r"(a[2]), "r"(a[3]), "r"(b[0]), "r"(b[1]));
}
__device__ __forceinline__ void ldsm_x4(uint32_t* r, uint32_t addr) {
    asm volatile("ldmatrix.sync.aligned.m8n8.x4.shared.b16 {%0,%1,%2,%3}, [%4];"
        : "=r"(r[0]), "=r"(r[1]), "=r"(r[2]), "=r"(r[3]) : "r"(addr));
}
__device__ __forceinline__ uint32_t smem_to_u32(const void* p) {
    uint32_t a;
    asm("{ .reg .u64 t; cvta.to.shared.u64 t, %1; cvt.u32.u64 %0, t; }" : "=r"(a) : "l"(p));
    return a;
}
__device__ __forceinline__ void cp16(uint32_t s, const void* g) {
    asm volatile("cp.async.cg.shared.global [%0], [%1], 16;" :: "r"(s), "l"(g));
}
#define CP_COMMIT() asm volatile("cp.async.commit_group;" ::: "memory")
#define CP_WAIT(N)  asm volatile("cp.async.wait_group %0;" :: "n"(N) : "memory")

__device__ __forceinline__ void packsplit(float a, float b, uint32_t& hi, uint32_t& lo) {
    __nv_bfloat162 h = __floats2bfloat162_rn(a, b);
    hi = *(uint32_t*)&h;
    float ra = a - __bfloat162float(h.x);
    float rb = b - __bfloat162float(h.y);
    __nv_bfloat162 l = __floats2bfloat162_rn(ra, rb);
    lo = *(uint32_t*)&l;
}
__device__ __forceinline__ float wv2(float4 s, float nfs, float APr, float ANr, unsigned bit) {
    bool p = s.x >= nfs;
    float w = (p ? APr : ANr) * (p ? s.y : s.z);
    return bit ? w : 0.f;
}
// round pair to bf16x2, return bits, add the ROUNDED values into dsum (consistency)
__device__ __forceinline__ uint32_t roundacc(float a, float b, float& dsum) {
    __nv_bfloat162 h = __floats2bfloat162_rn(a, b);
    dsum += __bfloat162float(h.x) + __bfloat162float(h.y);
    return *(uint32_t*)&h;
}

// ---------------------------------------------------------------- scratch
#define SCR_FLOATS (NN*DD + 3*HH*NN + 4*HH*NN + 3*NN + 4*NN + SPLIT*NN*DD + SPLIT*NN)
__device__ __align__(16) float g_scratch[SCR_FLOATS];
__device__ __align__(16) unsigned g_bits[NN*(NN/32)];
#define BF_ELEMS (2*NN*FF + 2*HH*FF*DD + 2*NN*FF + 2*NN*FF + 2*FF*DD + 2*NN*DD)
__device__ __align__(16) __nv_bfloat16 g_bf[BF_ELEMS];

// ---------------- prep: split x (z=0) + transpose/split W, Wo (z=1) ----------------
__global__ __launch_bounds__(256) void k_prep(
    const float* __restrict__ x, const float* __restrict__ W, const float* __restrict__ Wo,
    __nv_bfloat16* __restrict__ x_hi, __nv_bfloat16* __restrict__ x_lo,
    __nv_bfloat16* __restrict__ Wt_hi, __nv_bfloat16* __restrict__ Wt_lo,
    __nv_bfloat16* __restrict__ Wot_hi, __nv_bfloat16* __restrict__ Wot_lo)
{
    __shared__ float tile[32][33];
    int t = threadIdx.x;
    if (blockIdx.z == 0) {
        int i = blockIdx.x*256 + t;
        if (i >= NN*FF/4) return;
        float4 v = *(const float4*)(x + (size_t)i*4);
        uint32_t h0, l0, h1, l1;
        packsplit(v.x, v.y, h0, l0);
        packsplit(v.z, v.w, h1, l1);
        *(uint32_t*)(x_hi + (size_t)i*4)     = h0;
        *(uint32_t*)(x_hi + (size_t)i*4 + 2) = h1;
        *(uint32_t*)(x_lo + (size_t)i*4)     = l0;
        *(uint32_t*)(x_lo + (size_t)i*4 + 2) = l1;
        return;
    }
    const float* A; __nv_bfloat16 *Thi, *Tlo;
    int bxx, byy;
    int bx = blockIdx.x;
    if (bx < 256) {
        int h = bx >> 5, rem = bx & 31;
        bxx = rem & 15; byy = rem >> 4;
        A = W + (size_t)h*FF*DD;
        Thi = Wt_hi + (size_t)h*FF*DD;
        Tlo = Wt_lo + (size_t)h*FF*DD;
    } else if (bx < 288) {
        int idx = bx - 256;
        bxx = idx & 15; byy = idx >> 4;
        A = Wo; Thi = Wot_hi; Tlo = Wot_lo;
    } else return;
    int n0 = bxx*32, c0 = byy*32;
    int tx = t & 31, ty = t >> 5;
    #pragma unroll
    for (int i = 0; i < 4; i++) {
        int nr = ty*4 + i;
        tile[nr][tx] = A[(size_t)(n0+nr)*DD + c0 + tx];
    }
    __syncthreads();
    #pragma unroll
    for (int i = 0; i < 4; i++) {
        int cr = ty*4 + i;
        float v = tile[tx][cr];
        __nv_bfloat16 h = __float2bfloat16(v);
        Thi[(size_t)(c0+cr)*FF + n0 + tx] = h;
        Tlo[(size_t)(c0+cr)*FF + n0 + tx] = __float2bfloat16(v - __bfloat162float(h));
    }
}

// ---------------- adj -> bitmask ----------------
__global__ void k_bits(const int* __restrict__ adj, unsigned* __restrict__ bits) {
    int gw = (blockIdx.x * blockDim.x + threadIdx.x) >> 5;
    int lane = threadIdx.x & 31;
    if (gw >= NN*(NN/32)) return;
    int v = adj[(size_t)gw*32 + lane];
    unsigned b = __ballot_sync(0xFFFFFFFFu, v > 0);
    if (lane == 0) bits[gw] = b;
}

// ---------------- fused HMMA GEMM + fexp + transposed split epilogue ----------------
#define G_AH 0
#define G_AL 18432
#define G_BH 36864
#define G_BL 46080
#define G_STAGE 55296
#define SMEM_G (2*G_STAGE)

__global__ __launch_bounds__(256, 2) void k_gemm_f(
    const __nv_bfloat16* __restrict__ Ah, const __nv_bfloat16* __restrict__ Al,
    const __nv_bfloat16* __restrict__ Bh, const __nv_bfloat16* __restrict__ Bl, int K,
    const float* __restrict__ av_src, const float* __restrict__ av_dst,
    float* __restrict__ fsrc, float* __restrict__ Ap, float* __restrict__ An,
    float4* __restrict__ pk,
    __nv_bfloat16* __restrict__ outT_hi, __nv_bfloat16* __restrict__ outT_lo)
{
    extern __shared__ char smem[];
    uint32_t sb = smem_to_u32(smem);
    int t = threadIdx.x;
    int wid = t >> 5, lane = t & 31;
    int n0 = blockIdx.x*128, c0 = blockIdx.y*64;
    int fbase = blockIdx.y*NN;
    float acc[8][4];
    #pragma unroll
    for (int i = 0; i < 8; i++)
        #pragma unroll
        for (int j = 0; j < 4; j++) acc[i][j] = 0.f;

    int mrow = wid*16 + (lane&7) + ((lane>>3)&1)*8;
    uint32_t aOff = (uint32_t)(mrow*72 + (lane>>4)*8)*2;
    uint32_t bOff = (uint32_t)((lane&7)*72 + (lane>>3)*8)*2;

    int chunks = K/64;
    auto stage = [&](int kc) {
        uint32_t dst = sb + (uint32_t)(kc & 1)*G_STAGE;
        int k0 = kc*64;
        #pragma unroll
        for (int i = 0; i < 4; i++) {
            int idx = t + i*256;
            int row = idx >> 3, k16 = idx & 7;
            cp16(dst + G_AH + row*144 + k16*16, Ah + (size_t)(n0+row)*K + k0 + k16*8);
            cp16(dst + G_AL + row*144 + k16*16, Al + (size_t)(n0+row)*K + k0 + k16*8);
        }
        #pragma unroll
        for (int i = 0; i < 2; i++) {
            int idx = t + i*256;
            int col = idx >> 3, k16 = idx & 7;
            cp16(dst + G_BH + col*144 + k16*16, Bh + (size_t)(c0+col)*K + k0 + k16*8);
            cp16(dst + G_BL + col*144 + k16*16, Bl + (size_t)(c0+col)*K + k0 + k16*8);
        }
        CP_COMMIT();
    };

    stage(0);
    for (int kc = 0; kc < chunks; kc++) {
        if (kc + 1 < chunks) { stage(kc + 1); CP_WAIT(1); }
        else                 { CP_WAIT(0); }
        __syncthreads();
        uint32_t sbuf = sb + (uint32_t)(kc & 1)*G_STAGE;
        #pragma unroll
        for (int ko = 0; ko < 2; ko++) {
            uint32_t ah[8], al[8];
            ldsm_x4(ah+0, sbuf + G_AH + aOff + ko*64);
            ldsm_x4(ah+4, sbuf + G_AH + aOff + ko*64 + 32);
            ldsm_x4(al+0, sbuf + G_AL + aOff + ko*64);
            ldsm_x4(al+4, sbuf + G_AL + aOff + ko*64 + 32);
            #pragma unroll
            for (int dt = 0; dt < 8; dt++) {
                uint32_t bh[4], bl[4];
                ldsm_x4(bh, sbuf + G_BH + bOff + dt*1152 + ko*64);
                ldsm_x4(bl, sbuf + G_BL + bOff + dt*1152 + ko*64);
                mma_bf16(acc[dt], ah+0, bh+0);
                mma_bf16(acc[dt], ah+4, bh+2);
                mma_bf16(acc[dt], ah+0, bl+0);
                mma_bf16(acc[dt], ah+4, bl+2);
                mma_bf16(acc[dt], al+0, bh+0);
                mma_bf16(acc[dt], al+4, bh+2);
            }
        }
        __syncthreads();
    }

    int qr = lane >> 2, c2 = (lane & 3)*2;
    int r0 = wid*16 + qr, r1 = r0 + 8;

    float fs0 = 0.f, fs1 = 0.f, fd0 = 0.f, fd1 = 0.f;
    #pragma unroll
    for (int dt = 0; dt < 8; dt++) {
        float a0 = av_src[c0 + dt*8 + c2], a1 = av_src[c0 + dt*8 + c2 + 1];
        float b0 = av_dst[c0 + dt*8 + c2], b1 = av_dst[c0 + dt*8 + c2 + 1];
        fs0 += acc[dt][0]*a0 + acc[dt][1]*a1;
        fs1 += acc[dt][2]*a0 + acc[dt][3]*a1;
        fd0 += acc[dt][0]*b0 + acc[dt][1]*b1;
        fd1 += acc[dt][2]*b0 + acc[dt][3]*b1;
    }
    #pragma unroll
    for (int o = 1; o <= 2; o <<= 1) {
        fs0 += __shfl_xor_sync(0xFFFFFFFFu, fs0, o);
        fs1 += __shfl_xor_sync(0xFFFFFFFFu, fs1, o);
        fd0 += __shfl_xor_sync(0xFFFFFFFFu, fd0, o);
        fd1 += __shfl_xor_sync(0xFFFFFFFFu, fd1, o);
    }
    if ((lane & 3) == 0) {
        int na = fbase + n0 + r0, nb = fbase + n0 + r1;
        fsrc[na] = fs0; Ap[na] = expf(fs0); An[na] = expf(0.2f*fs0);
        pk[na] = make_float4(fd0, expf(fd0), expf(0.2f*fd0), 0.f);
        fsrc[nb] = fs1; Ap[nb] = expf(fs1); An[nb] = expf(0.2f*fs1);
        pk[nb] = make_float4(fd1, expf(fd1), expf(0.2f*fd1), 0.f);
    }

    float* sT = (float*)smem;
    #pragma unroll
    for (int dt = 0; dt < 8; dt++) {
        int c = dt*8 + c2;
        sT[(c  )*132 + r0] = acc[dt][0];
        sT[(c+1)*132 + r0] = acc[dt][1];
        sT[(c  )*132 + r1] = acc[dt][2];
        sT[(c+1)*132 + r1] = acc[dt][3];
    }
    __syncthreads();
    {
        int c = t >> 2;
        int nb = (t & 3)*32;
        const float* src = sT + c*132 + nb;
        __nv_bfloat16* dh = outT_hi + (size_t)(c0 + c)*NN + n0 + nb;
        __nv_bfloat16* dl = outT_lo + (size_t)(c0 + c)*NN + n0 + nb;
        #pragma unroll
        for (int j = 0; j < 16; j++) {
            uint32_t hi, lo;
            packsplit(src[j*2], src[j*2+1], hi, lo);
            *(uint32_t*)(dh + j*2) = hi;
            *(uint32_t*)(dl + j*2) = lo;
        }
    }
}

// ------------- attn: 256-row tile, 128-m chunks, 3-stage cp.async -------------
#define VH_OFF 0
#define VL_OFF 17408
#define PK_OFF 34816
#define STAGE_B 36864
#define SMEM_ATT (3*STAGE_B)

__global__ __launch_bounds__(256) void k_attn_mma(
    const __nv_bfloat16* __restrict__ VT_hi,
    const __nv_bfloat16* __restrict__ VT_lo,
    const float* __restrict__ fsrc, const float* __restrict__ Ap, const float* __restrict__ An,
    const float4* __restrict__ pk,
    const unsigned* __restrict__ bits,
    __nv_bfloat16* __restrict__ out_hi, __nv_bfloat16* __restrict__ out_lo, int ldout,
    int mPerCta, float* __restrict__ pnum, float* __restrict__ pden, int partial)
{
    extern __shared__ char smem[];
    uint32_t sb = smem_to_u32(smem);
    int t = threadIdx.x;
    int wid = t >> 5, lane = t & 31;
    int head = blockIdx.y;
    int seg = blockIdx.z;
    int n0 = blockIdx.x * 256;
    int fbase = head * NN;
    int coloff = head * 64;
    int mStart = seg * mPerCta;
    int iters = mPerCta / 128;

    int qr = lane >> 2;
    int c2 = (lane & 3) * 2;
    int rbase = n0 + wid*32;

    float nfs[2][2], Apx[2][2], Anx[2][2];
    const unsigned* brow[2][2];
    #pragma unroll
    for (int g = 0; g < 2; g++)
        #pragma unroll
        for (int s = 0; s < 2; s++) {
            int r = rbase + g*16 + s*8 + qr;
            nfs[g][s] = -fsrc[fbase + r];
            Apx[g][s] = Ap[fbase + r];
            Anx[g][s] = An[fbase + r];
            brow[g][s] = bits + (size_t)r*(NN/32);
        }

    float acc[2][8][4];
    #pragma unroll
    for (int g = 0; g < 2; g++)
        #pragma unroll
        for (int i = 0; i < 8; i++)
            #pragma unroll
            for (int j = 0; j < 4; j++) acc[g][i][j] = 0.f;
    float ds[2][2] = {{0.f, 0.f}, {0.f, 0.f}};

    auto stage = [&](int it) {
        uint32_t dst = sb + (uint32_t)(it % 3)*STAGE_B;
        int m0 = mStart + it*128;
        #pragma unroll
        for (int i = 0; i < 4; i++) {
            int idx = t + i*256;            // 0..1023
            int d = idx >> 4, k16 = idx & 15;
            cp16(dst + VH_OFF + d*272 + k16*16, VT_hi + (size_t)(coloff + d)*NN + m0 + k16*8);
            cp16(dst + VL_OFF + d*272 + k16*16, VT_lo + (size_t)(coloff + d)*NN + m0 + k16*8);
        }
        if (t < 128) cp16(dst + PK_OFF + t*16, pk + fbase + m0 + t);
        CP_COMMIT();
    };

    stage(0);
    if (iters > 1) stage(1);
    uint32_t bOff = (uint32_t)((lane & 7)*272 + (lane >> 3)*16);

    for (int it = 0; it < iters; it++) {
        if (it + 2 < iters)      { stage(it + 2); CP_WAIT(2); }
        else if (it + 1 < iters) { CP_WAIT(1); }
        else                     { CP_WAIT(0); }
        __syncthreads();

        int buf = it % 3;
        uint32_t sbuf = sb + (uint32_t)buf*STAGE_B;
        const float4* pks = (const float4*)(smem + buf*STAGE_B + PK_OFF);
        int m0 = mStart + it*128;

        // 4 mask words per row for this 128-m chunk (16B-aligned)
        unsigned bw[2][2][4];
        #pragma unroll
        for (int g = 0; g < 2; g++)
            #pragma unroll
            for (int s = 0; s < 2; s++)
                *(uint4*)bw[g][s] = *(const uint4*)(brow[g][s] + (m0 >> 5));

        #pragma unroll
        for (int half = 0; half < 2; half++) {
            uint32_t ah[2][4][4];
            #pragma unroll
            for (int kc = 0; kc < 4; kc++) {
                int mloc = half*64 + kc*16;
                int mA = mloc + c2, mB = mA + 8;
                float4 sA0 = pks[mA], sA1 = pks[mA+1];
                float4 sB0 = pks[mB], sB1 = pks[mB+1];
                int wq = mA >> 5;
                int jA = mA & 31, jB = mB & 31;
                #pragma unroll
                for (int g = 0; g < 2; g++) {
                    #pragma unroll
                    for (int s = 0; s < 2; s++) {
                        unsigned word = bw[g][s][wq];
                        float w0 = wv2(sA0, nfs[g][s], Apx[g][s], Anx[g][s], (word >> jA) & 1u);
                        float w1 = wv2(sA1, nfs[g][s], Apx[g][s], Anx[g][s], (word >> (jA+1)) & 1u);
                        float w2 = wv2(sB0, nfs[g][s], Apx[g][s], Anx[g][s], (word >> jB) & 1u);
                        float w3 = wv2(sB1, nfs[g][s], Apx[g][s], Anx[g][s], (word >> (jB+1)) & 1u);
                        ah[g][kc][s]     = roundacc(w0, w1, ds[g][s]);
                        ah[g][kc][s + 2] = roundacc(w2, w3, ds[g][s]);
                    }
                }
            }
            #pragma unroll
            for (int ko = 0; ko < 2; ko++) {
                #pragma unroll
                for (int dt = 0; dt < 8; dt++) {
                    uint32_t bh[4], bl[4];
                    ldsm_x4(bh, sbuf + VH_OFF + bOff + dt*2176 + (half*2+ko)*64);
                    ldsm_x4(bl, sbuf + VL_OFF + bOff + dt*2176 + (half*2+ko)*64);
                    #pragma unroll
                    for (int g = 0; g < 2; g++) {
                        mma_bf16(acc[g][dt], ah[g][2*ko],   bh+0);
                        mma_bf16(acc[g][dt], ah[g][2*ko+1], bh+2);
                        mma_bf16(acc[g][dt], ah[g][2*ko],   bl+0);
                        mma_bf16(acc[g][dt], ah[g][2*ko+1], bl+2);
                    }
                }
            }
        }
        __syncthreads();
    }

    #pragma unroll
    for (int g = 0; g < 2; g++)
        #pragma unroll
        for (int s = 0; s < 2; s++) {
            ds[g][s] += __shfl_xor_sync(0xFFFFFFFFu, ds[g][s], 1);
            ds[g][s] += __shfl_xor_sync(0xFFFFFFFFu, ds[g][s], 2);
        }

    if (partial) {
        if ((lane & 3) == 0) {
            #pragma unroll
            for (int g = 0; g < 2; g++)
                #pragma unroll
                for (int s = 0; s < 2; s++)
                    pden[(size_t)seg*NN + rbase + g*16 + s*8 + qr] = ds[g][s];
        }
        #pragma unroll
        for (int g = 0; g < 2; g++) {
            float* p0 = pnum + ((size_t)seg*NN + rbase + g*16 + qr)*64;
            float* p1 = pnum + ((size_t)seg*NN + rbase + g*16 + 8 + qr)*64;
            #pragma unroll
            for (int dt = 0; dt < 8; dt++) {
                *(float2*)(p0 + dt*8 + c2) = make_float2(acc[g][dt][0], acc[g][dt][1]);
                *(float2*)(p1 + dt*8 + c2) = make_float2(acc[g][dt][2], acc[g][dt][3]);
            }
        }
    } else {
        #pragma unroll
        for (int g = 0; g < 2; g++) {
            float inv0 = 1.0f / ds[g][0], inv1 = 1.0f / ds[g][1];
            int r0 = rbase + g*16 + qr, r1 = r0 + 8;
            #pragma unroll
            for (int dt = 0; dt < 8; dt++) {
                float z0 = acc[g][dt][0]*inv0, z1 = acc[g][dt][1]*inv0;
                float z2 = acc[g][dt][2]*inv1, z3 = acc[g][dt][3]*inv1;
                z0 = (z0 > 0.f) ? z0 : expm1f(z0);
                z1 = (z1 > 0.f) ? z1 : expm1f(z1);
                z2 = (z2 > 0.f) ? z2 : expm1f(z2);
                z3 = (z3 > 0.f) ? z3 : expm1f(z3);
                uint32_t h0, l0, h1, l1;
                packsplit(z0, z1, h0, l0);
                packsplit(z2, z3, h1, l1);
                size_t o0 = (size_t)r0*ldout + coloff + dt*8 + c2;
                size_t o1 = (size_t)r1*ldout + coloff + dt*8 + c2;
                *(uint32_t*)(out_hi + o0) = h0;
                *(uint32_t*)(out_lo + o0) = l0;
                *(uint32_t*)(out_hi + o1) = h1;
                *(uint32_t*)(out_lo + o1) = l1;
            }
        }
    }
}

// ------------- combine K-split partials -------------
__global__ void k_comb(const float* __restrict__ pnum, const float* __restrict__ pden,
                       float* __restrict__ h2)
{
    int gw = (blockIdx.x*blockDim.x + threadIdx.x) >> 5;
    int lane = threadIdx.x & 31;
    if (gw >= NN) return;
    float den = 0.f;
    #pragma unroll
    for (int s = 0; s < SPLIT; s++) den += pden[(size_t)s*NN + gw];
    float a0 = 0.f, a1 = 0.f;
    #pragma unroll
    for (int s = 0; s < SPLIT; s++) {
        const float* p = pnum + ((size_t)s*NN + gw)*64;
        a0 += p[lane]; a1 += p[lane+32];
    }
    float inv = 1.0f / den;
    h2[(size_t)gw*64 + lane]      = a0*inv;
    h2[(size_t)gw*64 + lane + 32] = a1*inv;
}

// ------------- ELU + row log_softmax -------------
__global__ void k_final(const float* __restrict__ h2, float* __restrict__ out) {
    int gw = (blockIdx.x*blockDim.x + threadIdx.x) >> 5;
    int lane = threadIdx.x & 31;
    if (gw >= NN) return;
    const float* row = h2 + (size_t)gw*64;
    float z0 = row[lane], z1 = row[lane+32];
    z0 = (z0 > 0.f) ? z0 : expm1f(z0);
    z1 = (z1 > 0.f) ? z1 : expm1f(z1);
    float mx = fmaxf(z0, z1);
    #pragma unroll
    for (int o = 16; o; o >>= 1) mx = fmaxf(mx, __shfl_xor_sync(0xFFFFFFFFu, mx, o));
    float se = expf(z0 - mx) + expf(z1 - mx);
    #pragma unroll
    for (int o = 16; o; o >>= 1) se += __shfl_xor_sync(0xFFFFFFFFu, se, o);
    float lse = mx + logf(se);
    out[(size_t)gw*64 + lane]      = z0 - lse;
    out[(size_t)gw*64 + lane + 32] = z1 - lse;
}

extern "C" void kernel_launch(void* const* d_in, const int* in_sizes, int n_in,
                              void* d_out, int out_size)
{
    const float* x     = (const float*)d_in[0];
    const int*   adj   = (const int*)  d_in[1];
    const float* W     = (const float*)d_in[2];
    const float* asrc  = (const float*)d_in[3];
    const float* adst  = (const float*)d_in[4];
    const float* Wo    = (const float*)d_in[5];
    const float* aosrc = (const float*)d_in[6];
    const float* aodst = (const float*)d_in[7];
    float* out = (float*)d_out;

    void* sp = nullptr;  cudaGetSymbolAddress(&sp, g_scratch);
    void* bpv = nullptr; cudaGetSymbolAddress(&bpv, g_bits);
    void* bfv = nullptr; cudaGetSymbolAddress(&bfv, g_bf);
    float* S = (float*)sp;
    unsigned* bits = (unsigned*)bpv;
    __nv_bfloat16* BF = (__nv_bfloat16*)bfv;

    float* h2    = S;
    float* fsrcM = h2  + (size_t)NN*DD;
    float* ApM   = fsrcM + (size_t)HH*NN;
    float* AnM   = ApM   + (size_t)HH*NN;
    float4* pkM  = (float4*)(AnM + (size_t)HH*NN);
    float* fsrcO = (float*)(pkM + (size_t)HH*NN);
    float* ApO   = fsrcO + NN;
    float* AnO   = ApO + NN;
    float4* pkO  = (float4*)(AnO + NN);
    float* pnum  = (float*)(pkO + NN);
    float* pden  = pnum + (size_t)SPLIT*NN*DD;

    __nv_bfloat16* x_hi   = BF;
    __nv_bfloat16* x_lo   = x_hi   + (size_t)NN*FF;
    __nv_bfloat16* Wt_hi  = x_lo   + (size_t)NN*FF;
    __nv_bfloat16* Wt_lo  = Wt_hi  + (size_t)HH*FF*DD;
    __nv_bfloat16* WhT_hi = Wt_lo  + (size_t)HH*FF*DD;
    __nv_bfloat16* WhT_lo = WhT_hi + (size_t)NN*FF;
    __nv_bfloat16* hc_hi  = WhT_lo + (size_t)NN*FF;
    __nv_bfloat16* hc_lo  = hc_hi  + (size_t)NN*FF;
    __nv_bfloat16* Wot_hi = hc_lo  + (size_t)NN*FF;
    __nv_bfloat16* Wot_lo = Wot_hi + (size_t)FF*DD;
    __nv_bfloat16* WoT_hi = Wot_lo + (size_t)FF*DD;
    __nv_bfloat16* WoT_lo = WoT_hi + (size_t)NN*DD;

    cudaFuncSetAttribute(k_gemm_f, cudaFuncAttributeMaxDynamicSharedMemorySize, SMEM_G);
    cudaFuncSetAttribute(k_attn_mma, cudaFuncAttributeMaxDynamicSharedMemorySize, SMEM_ATT);

    // 0) prep
    k_prep<<<dim3(2048, 1, 2), 256>>>(x, W, Wo, x_hi, x_lo, Wt_hi, Wt_lo, Wot_hi, Wot_lo);
    // 1) adj -> bitmask
    {
        long long threads = (long long)NN*(NN/32)*32;
        k_bits<<<(unsigned)((threads + 255)/256), 256>>>(adj, bits);
    }
    // 2) gemm1 fused
    k_gemm_f<<<dim3(NN/128, FF/64), 256, SMEM_G>>>(x_hi, x_lo, Wt_hi, Wt_lo, FF,
        asrc, adst, fsrcM, ApM, AnM, pkM, WhT_hi, WhT_lo);
    // 3) main attention (256-row tiles)
    k_attn_mma<<<dim3(NN/256, HH, 1), 256, SMEM_ATT>>>(WhT_hi, WhT_lo,
        fsrcM, ApM, AnM, pkM, bits, hc_hi, hc_lo, FF, NN, nullptr, nullptr, 0);
    // 4) gemm2 fused
    k_gemm_f<<<dim3(NN/128, 1), 256, SMEM_G>>>(hc_hi, hc_lo, Wot_hi, Wot_lo, FF,
        aosrc, aodst, fsrcO, ApO, AnO, pkO, WoT_hi, WoT_lo);
    // 5) out-head attention, 8-way K-split (256-row tiles)
    k_attn_mma<<<dim3(NN/256, 1, SPLIT), 256, SMEM_ATT>>>(WoT_hi, WoT_lo,
        fsrcO, ApO, AnO, pkO, bits, nullptr, nullptr, DD, NN/SPLIT, pnum, pden, 1);
    // 6) combine + 7) final
    k_comb<<<(NN*32 + 255)/256, 256>>>(pnum, pden, h2);
    k_final<<<(NN*32 + 255)/256, 256>>>(h2, out);
}

// round 8
// speedup vs baseline: 3.9719x; 1.1539x over previous
#include <cuda_runtime.h>
#include <cuda_bf16.h>
#include <cstdint>

#define NN 4096
#define FF 512
#define DD 64
#define HH 8
#define SPLIT 8

// ---------------------------------------------------------------- helpers
__device__ __forceinline__ void mma_bf16(float* d, const uint32_t* a, const uint32_t* b) {
    asm volatile("mma.sync.aligned.m16n8k16.row.col.f32.bf16.bf16.f32 "
        "{%0,%1,%2,%3}, {%4,%5,%6,%7}, {%8,%9}, {%0,%1,%2,%3};"
        : "+f"(d[0]), "+f"(d[1]), "+f"(d[2]), "+f"(d[3])
        : "r"(a[0]), "r"(a[1]), "r"(a[2]), "r"(a[3]), "r"(b[0]), "r"(b[1]));
}
__device__ __forceinline__ void ldsm_x4(uint32_t* r, uint32_t addr) {
    asm volatile("ldmatrix.sync.aligned.m8n8.x4.shared.b16 {%0,%1,%2,%3}, [%4];"
        : "=r"(r[0]), "=r"(r[1]), "=r"(r[2]), "=r"(r[3]) : "r"(addr));
}
__device__ __forceinline__ uint32_t smem_to_u32(const void* p) {
    uint32_t a;
    asm("{ .reg .u64 t; cvta.to.shared.u64 t, %1; cvt.u32.u64 %0, t; }" : "=r"(a) : "l"(p));
    return a;
}
__device__ __forceinline__ void cp16(uint32_t s, const void* g) {
    asm volatile("cp.async.cg.shared.global [%0], [%1], 16;" :: "r"(s), "l"(g));
}
#define CP_COMMIT() asm volatile("cp.async.commit_group;" ::: "memory")
#define CP_WAIT(N)  asm volatile("cp.async.wait_group %0;" :: "n"(N) : "memory")

__device__ __forceinline__ void packsplit(float a, float b, uint32_t& hi, uint32_t& lo) {
    __nv_bfloat162 h = __floats2bfloat162_rn(a, b);
    hi = *(uint32_t*)&h;
    float ra = a - __bfloat162float(h.x);
    float rb = b - __bfloat162float(h.y);
    __nv_bfloat162 l = __floats2bfloat162_rn(ra, rb);
    lo = *(uint32_t*)&l;
}
__device__ __forceinline__ uint32_t pack_bf2(float a, float b) {
    __nv_bfloat162 p = __floats2bfloat162_rn(a, b);
    return *(uint32_t*)&p;
}
// w = exp(lrelu(fs+fd)) = max(Ap*Bp, An*Bn)  (exp is monotone), masked
__device__ __forceinline__ float wv3(float2 s, float APr, float ANr, unsigned bit) {
    float w = fmaxf(APr * s.x, ANr * s.y);
    return bit ? w : 0.f;
}

// ---------------------------------------------------------------- scratch
#define SCR_FLOATS (NN*DD + 2*HH*NN + 2*HH*NN + 2*NN + 2*NN + SPLIT*NN*DD + SPLIT*NN)
__device__ __align__(16) float g_scratch[SCR_FLOATS];
__device__ __align__(16) unsigned g_bits[NN*(NN/32)];
#define BF_ELEMS (2*NN*FF + 2*HH*FF*DD + 2*NN*FF + 2*NN*FF + 2*FF*DD + 2*NN*DD)
__device__ __align__(16) __nv_bfloat16 g_bf[BF_ELEMS];

// ---------------- prep: split x (z=0) + transpose/split W, Wo (z=1) ----------------
__global__ __launch_bounds__(256) void k_prep(
    const float* __restrict__ x, const float* __restrict__ W, const float* __restrict__ Wo,
    __nv_bfloat16* __restrict__ x_hi, __nv_bfloat16* __restrict__ x_lo,
    __nv_bfloat16* __restrict__ Wt_hi, __nv_bfloat16* __restrict__ Wt_lo,
    __nv_bfloat16* __restrict__ Wot_hi, __nv_bfloat16* __restrict__ Wot_lo)
{
    __shared__ float tile[32][33];
    int t = threadIdx.x;
    if (blockIdx.z == 0) {
        int i = blockIdx.x*256 + t;
        if (i >= NN*FF/4) return;
        float4 v = *(const float4*)(x + (size_t)i*4);
        uint32_t h0, l0, h1, l1;
        packsplit(v.x, v.y, h0, l0);
        packsplit(v.z, v.w, h1, l1);
        *(uint32_t*)(x_hi + (size_t)i*4)     = h0;
        *(uint32_t*)(x_hi + (size_t)i*4 + 2) = h1;
        *(uint32_t*)(x_lo + (size_t)i*4)     = l0;
        *(uint32_t*)(x_lo + (size_t)i*4 + 2) = l1;
        return;
    }
    const float* A; __nv_bfloat16 *Thi, *Tlo;
    int bxx, byy;
    int bx = blockIdx.x;
    if (bx < 256) {
        int h = bx >> 5, rem = bx & 31;
        bxx = rem & 15; byy = rem >> 4;
        A = W + (size_t)h*FF*DD;
        Thi = Wt_hi + (size_t)h*FF*DD;
        Tlo = Wt_lo + (size_t)h*FF*DD;
    } else if (bx < 288) {
        int idx = bx - 256;
        bxx = idx & 15; byy = idx >> 4;
        A = Wo; Thi = Wot_hi; Tlo = Wot_lo;
    } else return;
    int n0 = bxx*32, c0 = byy*32;
    int tx = t & 31, ty = t >> 5;
    #pragma unroll
    for (int i = 0; i < 4; i++) {
        int nr = ty*4 + i;
        tile[nr][tx] = A[(size_t)(n0+nr)*DD + c0 + tx];
    }
    __syncthreads();
    #pragma unroll
    for (int i = 0; i < 4; i++) {
        int cr = ty*4 + i;
        float v = tile[tx][cr];
        __nv_bfloat16 h = __float2bfloat16(v);
        Thi[(size_t)(c0+cr)*FF + n0 + tx] = h;
        Tlo[(size_t)(c0+cr)*FF + n0 + tx] = __float2bfloat16(v - __bfloat162float(h));
    }
}

// ---------------- adj -> bitmask ----------------
__global__ void k_bits(const int* __restrict__ adj, unsigned* __restrict__ bits) {
    int gw = (blockIdx.x * blockDim.x + threadIdx.x) >> 5;
    int lane = threadIdx.x & 31;
    if (gw >= NN*(NN/32)) return;
    int v = adj[(size_t)gw*32 + lane];
    unsigned b = __ballot_sync(0xFFFFFFFFu, v > 0);
    if (lane == 0) bits[gw] = b;
}

// ---------------- fused HMMA GEMM + fexp + transposed split epilogue ----------------
#define G_AH 0
#define G_AL 18432
#define G_BH 36864
#define G_BL 46080
#define G_STAGE 55296
#define SMEM_G (2*G_STAGE)

__global__ __launch_bounds__(256, 2) void k_gemm_f(
    const __nv_bfloat16* __restrict__ Ah, const __nv_bfloat16* __restrict__ Al,
    const __nv_bfloat16* __restrict__ Bh, const __nv_bfloat16* __restrict__ Bl, int K,
    const float* __restrict__ av_src, const float* __restrict__ av_dst,
    float* __restrict__ Ap, float* __restrict__ An, float2* __restrict__ pk,
    __nv_bfloat16* __restrict__ outT_hi, __nv_bfloat16* __restrict__ outT_lo)
{
    extern __shared__ char smem[];
    uint32_t sb = smem_to_u32(smem);
    int t = threadIdx.x;
    int wid = t >> 5, lane = t & 31;
    int n0 = blockIdx.x*128, c0 = blockIdx.y*64;
    int fbase = blockIdx.y*NN;
    float acc[8][4];
    #pragma unroll
    for (int i = 0; i < 8; i++)
        #pragma unroll
        for (int j = 0; j < 4; j++) acc[i][j] = 0.f;

    int mrow = wid*16 + (lane&7) + ((lane>>3)&1)*8;
    uint32_t aOff = (uint32_t)(mrow*72 + (lane>>4)*8)*2;
    uint32_t bOff = (uint32_t)((lane&7)*72 + (lane>>3)*8)*2;

    int chunks = K/64;
    auto stage = [&](int kc) {
        uint32_t dst = sb + (uint32_t)(kc & 1)*G_STAGE;
        int k0 = kc*64;
        #pragma unroll
        for (int i = 0; i < 4; i++) {
            int idx = t + i*256;
            int row = idx >> 3, k16 = idx & 7;
            cp16(dst + G_AH + row*144 + k16*16, Ah + (size_t)(n0+row)*K + k0 + k16*8);
            cp16(dst + G_AL + row*144 + k16*16, Al + (size_t)(n0+row)*K + k0 + k16*8);
        }
        #pragma unroll
        for (int i = 0; i < 2; i++) {
            int idx = t + i*256;
            int col = idx >> 3, k16 = idx & 7;
            cp16(dst + G_BH + col*144 + k16*16, Bh + (size_t)(c0+col)*K + k0 + k16*8);
            cp16(dst + G_BL + col*144 + k16*16, Bl + (size_t)(c0+col)*K + k0 + k16*8);
        }
        CP_COMMIT();
    };

    stage(0);
    for (int kc = 0; kc < chunks; kc++) {
        if (kc + 1 < chunks) { stage(kc + 1); CP_WAIT(1); }
        else                 { CP_WAIT(0); }
        __syncthreads();
        uint32_t sbuf = sb + (uint32_t)(kc & 1)*G_STAGE;
        #pragma unroll
        for (int ko = 0; ko < 2; ko++) {
            uint32_t ah[8], al[8];
            ldsm_x4(ah+0, sbuf + G_AH + aOff + ko*64);
            ldsm_x4(ah+4, sbuf + G_AH + aOff + ko*64 + 32);
            ldsm_x4(al+0, sbuf + G_AL + aOff + ko*64);
            ldsm_x4(al+4, sbuf + G_AL + aOff + ko*64 + 32);
            #pragma unroll
            for (int dt = 0; dt < 8; dt++) {
                uint32_t bh[4], bl[4];
                ldsm_x4(bh, sbuf + G_BH + bOff + dt*1152 + ko*64);
                ldsm_x4(bl, sbuf + G_BL + bOff + dt*1152 + ko*64);
                mma_bf16(acc[dt], ah+0, bh+0);
                mma_bf16(acc[dt], ah+4, bh+2);
                mma_bf16(acc[dt], ah+0, bl+0);
                mma_bf16(acc[dt], ah+4, bl+2);
                mma_bf16(acc[dt], al+0, bh+0);
                mma_bf16(acc[dt], al+4, bh+2);
            }
        }
        __syncthreads();
    }

    int qr = lane >> 2, c2 = (lane & 3)*2;
    int r0 = wid*16 + qr, r1 = r0 + 8;

    float fs0 = 0.f, fs1 = 0.f, fd0 = 0.f, fd1 = 0.f;
    #pragma unroll
    for (int dt = 0; dt < 8; dt++) {
        float a0 = av_src[c0 + dt*8 + c2], a1 = av_src[c0 + dt*8 + c2 + 1];
        float b0 = av_dst[c0 + dt*8 + c2], b1 = av_dst[c0 + dt*8 + c2 + 1];
        fs0 += acc[dt][0]*a0 + acc[dt][1]*a1;
        fs1 += acc[dt][2]*a0 + acc[dt][3]*a1;
        fd0 += acc[dt][0]*b0 + acc[dt][1]*b1;
        fd1 += acc[dt][2]*b0 + acc[dt][3]*b1;
    }
    #pragma unroll
    for (int o = 1; o <= 2; o <<= 1) {
        fs0 += __shfl_xor_sync(0xFFFFFFFFu, fs0, o);
        fs1 += __shfl_xor_sync(0xFFFFFFFFu, fs1, o);
        fd0 += __shfl_xor_sync(0xFFFFFFFFu, fd0, o);
        fd1 += __shfl_xor_sync(0xFFFFFFFFu, fd1, o);
    }
    if ((lane & 3) == 0) {
        int na = fbase + n0 + r0, nb = fbase + n0 + r1;
        Ap[na] = expf(fs0); An[na] = expf(0.2f*fs0);
        pk[na] = make_float2(expf(fd0), expf(0.2f*fd0));
        Ap[nb] = expf(fs1); An[nb] = expf(0.2f*fs1);
        pk[nb] = make_float2(expf(fd1), expf(0.2f*fd1));
    }

    float* sT = (float*)smem;
    #pragma unroll
    for (int dt = 0; dt < 8; dt++) {
        int c = dt*8 + c2;
        sT[(c  )*132 + r0] = acc[dt][0];
        sT[(c+1)*132 + r0] = acc[dt][1];
        sT[(c  )*132 + r1] = acc[dt][2];
        sT[(c+1)*132 + r1] = acc[dt][3];
    }
    __syncthreads();
    {
        int c = t >> 2;
        int nb = (t & 3)*32;
        const float* src = sT + c*132 + nb;
        __nv_bfloat16* dh = outT_hi + (size_t)(c0 + c)*NN + n0 + nb;
        __nv_bfloat16* dl = outT_lo + (size_t)(c0 + c)*NN + n0 + nb;
        #pragma unroll
        for (int j = 0; j < 16; j++) {
            uint32_t hi, lo;
            packsplit(src[j*2], src[j*2+1], hi, lo);
            *(uint32_t*)(dh + j*2) = hi;
            *(uint32_t*)(dl + j*2) = lo;
        }
    }
}

// ------------- attn: 256-row tile, 128-m chunks, denominator via ones-column MMA -------------
#define VH_OFF 0
#define VL_OFF 17408
#define PK_OFF 34816
#define STAGE_B 35840
#define SMEM_ATT (3*STAGE_B)

__global__ __launch_bounds__(256) void k_attn_mma(
    const __nv_bfloat16* __restrict__ VT_hi,
    const __nv_bfloat16* __restrict__ VT_lo,
    const float* __restrict__ Ap, const float* __restrict__ An,
    const float2* __restrict__ pk,
    const unsigned* __restrict__ bits,
    __nv_bfloat16* __restrict__ out_hi, __nv_bfloat16* __restrict__ out_lo, int ldout,
    int mPerCta, float* __restrict__ pnum, float* __restrict__ pden, int partial)
{
    extern __shared__ char smem[];
    uint32_t sb = smem_to_u32(smem);
    int t = threadIdx.x;
    int wid = t >> 5, lane = t & 31;
    int head = blockIdx.y;
    int seg = blockIdx.z;
    int n0 = blockIdx.x * 256;
    int fbase = head * NN;
    int coloff = head * 64;
    int mStart = seg * mPerCta;
    int iters = mPerCta / 128;

    int qr = lane >> 2;
    int c2 = (lane & 3) * 2;
    int rbase = n0 + wid*32;

    float Apx[2][2], Anx[2][2];
    const unsigned* brow[2][2];
    #pragma unroll
    for (int g = 0; g < 2; g++)
        #pragma unroll
        for (int s = 0; s < 2; s++) {
            int r = rbase + g*16 + s*8 + qr;
            Apx[g][s] = Ap[fbase + r];
            Anx[g][s] = An[fbase + r];
            brow[g][s] = bits + (size_t)r*(NN/32);
        }

    float acc[2][8][4];
    float accD[2][4];
    #pragma unroll
    for (int g = 0; g < 2; g++) {
        #pragma unroll
        for (int i = 0; i < 8; i++)
            #pragma unroll
            for (int j = 0; j < 4; j++) acc[g][i][j] = 0.f;
        #pragma unroll
        for (int j = 0; j < 4; j++) accD[g][j] = 0.f;
    }

    const uint32_t ones2[2] = {0x3F803F80u, 0x3F803F80u};

    auto stage = [&](int it) {
        uint32_t dst = sb + (uint32_t)(it % 3)*STAGE_B;
        int m0 = mStart + it*128;
        #pragma unroll
        for (int i = 0; i < 4; i++) {
            int idx = t + i*256;            // 0..1023
            int d = idx >> 4, k16 = idx & 15;
            cp16(dst + VH_OFF + d*272 + k16*16, VT_hi + (size_t)(coloff + d)*NN + m0 + k16*8);
            cp16(dst + VL_OFF + d*272 + k16*16, VT_lo + (size_t)(coloff + d)*NN + m0 + k16*8);
        }
        if (t < 64) cp16(dst + PK_OFF + t*16, pk + fbase + m0 + t*2);
        CP_COMMIT();
    };

    stage(0);
    if (iters > 1) stage(1);
    uint32_t bOff = (uint32_t)((lane & 7)*272 + (lane >> 3)*16);

    for (int it = 0; it < iters; it++) {
        if (it + 2 < iters)      { stage(it + 2); CP_WAIT(2); }
        else if (it + 1 < iters) { CP_WAIT(1); }
        else                     { CP_WAIT(0); }
        __syncthreads();

        int buf = it % 3;
        uint32_t sbuf = sb + (uint32_t)buf*STAGE_B;
        const float2* pks = (const float2*)(smem + buf*STAGE_B + PK_OFF);
        int m0 = mStart + it*128;

        unsigned bw[2][2][4];
        #pragma unroll
        for (int g = 0; g < 2; g++)
            #pragma unroll
            for (int s = 0; s < 2; s++)
                *(uint4*)bw[g][s] = *(const uint4*)(brow[g][s] + (m0 >> 5));

        #pragma unroll
        for (int half = 0; half < 2; half++) {
            uint32_t ah[2][4][4];
            #pragma unroll
            for (int kc = 0; kc < 4; kc++) {
                int mloc = half*64 + kc*16;
                int mA = mloc + c2, mB = mA + 8;
                float2 sA0 = pks[mA], sA1 = pks[mA+1];
                float2 sB0 = pks[mB], sB1 = pks[mB+1];
                int wq = mA >> 5;
                int jA = mA & 31, jB = mB & 31;
                #pragma unroll
                for (int g = 0; g < 2; g++) {
                    #pragma unroll
                    for (int s = 0; s < 2; s++) {
                        unsigned word = bw[g][s][wq];
                        float w0 = wv3(sA0, Apx[g][s], Anx[g][s], (word >> jA) & 1u);
                        float w1 = wv3(sA1, Apx[g][s], Anx[g][s], (word >> (jA+1)) & 1u);
                        float w2 = wv3(sB0, Apx[g][s], Anx[g][s], (word >> jB) & 1u);
                        float w3 = wv3(sB1, Apx[g][s], Anx[g][s], (word >> (jB+1)) & 1u);
                        ah[g][kc][s]     = pack_bf2(w0, w1);
                        ah[g][kc][s + 2] = pack_bf2(w2, w3);
                    }
                }
            }
            #pragma unroll
            for (int ko = 0; ko < 2; ko++) {
                // denominator: ones-column MMA (B = 1.0, no LDSM, exact Σ w̃)
                #pragma unroll
                for (int g = 0; g < 2; g++) {
                    mma_bf16(accD[g], ah[g][2*ko],   ones2);
                    mma_bf16(accD[g], ah[g][2*ko+1], ones2);
                }
                #pragma unroll
                for (int dt = 0; dt < 8; dt++) {
                    uint32_t bh[4], bl[4];
                    ldsm_x4(bh, sbuf + VH_OFF + bOff + dt*2176 + (half*2+ko)*64);
                    ldsm_x4(bl, sbuf + VL_OFF + bOff + dt*2176 + (half*2+ko)*64);
                    #pragma unroll
                    for (int g = 0; g < 2; g++) {
                        mma_bf16(acc[g][dt], ah[g][2*ko],   bh+0);
                        mma_bf16(acc[g][dt], ah[g][2*ko+1], bh+2);
                        mma_bf16(acc[g][dt], ah[g][2*ko],   bl+0);
                        mma_bf16(acc[g][dt], ah[g][2*ko+1], bl+2);
                    }
                }
            }
        }
        __syncthreads();
    }

    if (partial) {
        if ((lane & 3) == 0) {
            #pragma unroll
            for (int g = 0; g < 2; g++) {
                pden[(size_t)seg*NN + rbase + g*16 + qr]     = accD[g][0];
                pden[(size_t)seg*NN + rbase + g*16 + 8 + qr] = accD[g][2];
            }
        }
        #pragma unroll
        for (int g = 0; g < 2; g++) {
            float* p0 = pnum + ((size_t)seg*NN + rbase + g*16 + qr)*64;
            float* p1 = pnum + ((size_t)seg*NN + rbase + g*16 + 8 + qr)*64;
            #pragma unroll
            for (int dt = 0; dt < 8; dt++) {
                *(float2*)(p0 + dt*8 + c2) = make_float2(acc[g][dt][0], acc[g][dt][1]);
                *(float2*)(p1 + dt*8 + c2) = make_float2(acc[g][dt][2], acc[g][dt][3]);
            }
        }
    } else {
        #pragma unroll
        for (int g = 0; g < 2; g++) {
            float inv0 = 1.0f / accD[g][0], inv1 = 1.0f / accD[g][2];
            int r0 = rbase + g*16 + qr, r1 = r0 + 8;
            #pragma unroll
            for (int dt = 0; dt < 8; dt++) {
                float z0 = acc[g][dt][0]*inv0, z1 = acc[g][dt][1]*inv0;
                float z2 = acc[g][dt][2]*inv1, z3 = acc[g][dt][3]*inv1;
                z0 = (z0 > 0.f) ? z0 : expm1f(z0);
                z1 = (z1 > 0.f) ? z1 : expm1f(z1);
                z2 = (z2 > 0.f) ? z2 : expm1f(z2);
                z3 = (z3 > 0.f) ? z3 : expm1f(z3);
                uint32_t h0, l0, h1, l1;
                packsplit(z0, z1, h0, l0);
                packsplit(z2, z3, h1, l1);
                size_t o0 = (size_t)r0*ldout + coloff + dt*8 + c2;
                size_t o1 = (size_t)r1*ldout + coloff + dt*8 + c2;
                *(uint32_t*)(out_hi + o0) = h0;
                *(uint32_t*)(out_lo + o0) = l0;
                *(uint32_t*)(out_hi + o1) = h1;
                *(uint32_t*)(out_lo + o1) = l1;
            }
        }
    }
}

// ------------- combine K-split partials -------------
__global__ void k_comb(const float* __restrict__ pnum, const float* __restrict__ pden,
                       float* __restrict__ h2)
{
    int gw = (blockIdx.x*blockDim.x + threadIdx.x) >> 5;
    int lane = threadIdx.x & 31;
    if (gw >= NN) return;
    float den = 0.f;
    #pragma unroll
    for (int s = 0; s < SPLIT; s++) den += pden[(size_t)s*NN + gw];
    float a0 = 0.f, a1 = 0.f;
    #pragma unroll
    for (int s = 0; s < SPLIT; s++) {
        const float* p = pnum + ((size_t)s*NN + gw)*64;
        a0 += p[lane]; a1 += p[lane+32];
    }
    float inv = 1.0f / den;
    h2[(size_t)gw*64 + lane]      = a0*inv;
    h2[(size_t)gw*64 + lane + 32] = a1*inv;
}

// ------------- ELU + row log_softmax -------------
__global__ void k_final(const float* __restrict__ h2, float* __restrict__ out) {
    int gw = (blockIdx.x*blockDim.x + threadIdx.x) >> 5;
    int lane = threadIdx.x & 31;
    if (gw >= NN) return;
    const float* row = h2 + (size_t)gw*64;
    float z0 = row[lane], z1 = row[lane+32];
    z0 = (z0 > 0.f) ? z0 : expm1f(z0);
    z1 = (z1 > 0.f) ? z1 : expm1f(z1);
    float mx = fmaxf(z0, z1);
    #pragma unroll
    for (int o = 16; o; o >>= 1) mx = fmaxf(mx, __shfl_xor_sync(0xFFFFFFFFu, mx, o));
    float se = expf(z0 - mx) + expf(z1 - mx);
    #pragma unroll
    for (int o = 16; o; o >>= 1) se += __shfl_xor_sync(0xFFFFFFFFu, se, o);
    float lse = mx + logf(se);
    out[(size_t)gw*64 + lane]      = z0 - lse;
    out[(size_t)gw*64 + lane + 32] = z1 - lse;
}

extern "C" void kernel_launch(void* const* d_in, const int* in_sizes, int n_in,
                              void* d_out, int out_size)
{
    const float* x     = (const float*)d_in[0];
    const int*   adj   = (const int*)  d_in[1];
    const float* W     = (const float*)d_in[2];
    const float* asrc  = (const float*)d_in[3];
    const float* adst  = (const float*)d_in[4];
    const float* Wo    = (const float*)d_in[5];
    const float* aosrc = (const float*)d_in[6];
    const float* aodst = (const float*)d_in[7];
    float* out = (float*)d_out;

    void* sp = nullptr;  cudaGetSymbolAddress(&sp, g_scratch);
    void* bpv = nullptr; cudaGetSymbolAddress(&bpv, g_bits);
    void* bfv = nullptr; cudaGetSymbolAddress(&bfv, g_bf);
    float* S = (float*)sp;
    unsigned* bits = (unsigned*)bpv;
    __nv_bfloat16* BF = (__nv_bfloat16*)bfv;

    float* h2    = S;
    float* ApM   = h2  + (size_t)NN*DD;
    float* AnM   = ApM + (size_t)HH*NN;
    float2* pkM  = (float2*)(AnM + (size_t)HH*NN);
    float* ApO   = (float*)(pkM + (size_t)HH*NN);
    float* AnO   = ApO + NN;
    float2* pkO  = (float2*)(AnO + NN);
    float* pnum  = (float*)(pkO + NN);
    float* pden  = pnum + (size_t)SPLIT*NN*DD;

    __nv_bfloat16* x_hi   = BF;
    __nv_bfloat16* x_lo   = x_hi   + (size_t)NN*FF;
    __nv_bfloat16* Wt_hi  = x_lo   + (size_t)NN*FF;
    __nv_bfloat16* Wt_lo  = Wt_hi  + (size_t)HH*FF*DD;
    __nv_bfloat16* WhT_hi = Wt_lo  + (size_t)HH*FF*DD;
    __nv_bfloat16* WhT_lo = WhT_hi + (size_t)NN*FF;
    __nv_bfloat16* hc_hi  = WhT_lo + (size_t)NN*FF;
    __nv_bfloat16* hc_lo  = hc_hi  + (size_t)NN*FF;
    __nv_bfloat16* Wot_hi = hc_lo  + (size_t)NN*FF;
    __nv_bfloat16* Wot_lo = Wot_hi + (size_t)FF*DD;
    __nv_bfloat16* WoT_hi = Wot_lo + (size_t)FF*DD;
    __nv_bfloat16* WoT_lo = WoT_hi + (size_t)NN*DD;

    cudaFuncSetAttribute(k_gemm_f, cudaFuncAttributeMaxDynamicSharedMemorySize, SMEM_G);
    cudaFuncSetAttribute(k_attn_mma, cudaFuncAttributeMaxDynamicSharedMemorySize, SMEM_ATT);

    // 0) prep
    k_prep<<<dim3(2048, 1, 2), 256>>>(x, W, Wo, x_hi, x_lo, Wt_hi, Wt_lo, Wot_hi, Wot_lo);
    // 1) adj -> bitmask
    {
        long long threads = (long long)NN*(NN/32)*32;
        k_bits<<<(unsigned)((threads + 255)/256), 256>>>(adj, bits);
    }
    // 2) gemm1 fused
    k_gemm_f<<<dim3(NN/128, FF/64), 256, SMEM_G>>>(x_hi, x_lo, Wt_hi, Wt_lo, FF,
        asrc, adst, ApM, AnM, pkM, WhT_hi, WhT_lo);
    // 3) main attention (256-row tiles)
    k_attn_mma<<<dim3(NN/256, HH, 1), 256, SMEM_ATT>>>(WhT_hi, WhT_lo,
        ApM, AnM, pkM, bits, hc_hi, hc_lo, FF, NN, nullptr, nullptr, 0);
    // 4) gemm2 fused
    k_gemm_f<<<dim3(NN/128, 1), 256, SMEM_G>>>(hc_hi, hc_lo, Wot_hi, Wot_lo, FF,
        aosrc, aodst, ApO, AnO, pkO, WoT_hi, WoT_lo);
    // 5) out-head attention, 8-way K-split (256-row tiles)
    k_attn_mma<<<dim3(NN/256, 1, SPLIT), 256, SMEM_ATT>>>(WoT_hi, WoT_lo,
        ApO, AnO, pkO, bits, nullptr, nullptr, DD, NN/SPLIT, pnum, pden, 1);
    // 6) combine + 7) final
    k_comb<<<(NN*32 + 255)/256, 256>>>(pnum, pden, h2);
    k_final<<<(NN*32 + 255)/256, 256>>>(h2, out);
}